// round 11
// baseline (speedup 1.0000x reference)
#include <cuda_runtime.h>
#include <cuda_fp16.h>
#include <math.h>
#include <stdint.h>

#define Nn 2048
#define Dd 512
#define Hh 8
#define Ff 2048
#define EDd 64
#define Pp 4
#define Ee 32768

typedef __half h16;

// ---------------- static scratch (no allocations allowed) ----------------
__device__ float g_Sf[(size_t)Hh * Nn * Nn];      // 128 MB scores (+ split-K partials reuse)
__device__ float g_x1[Nn * Dd];
__device__ float g_dmat[Hh * Ee * Pp];
__device__ float g_bqkv[24 * Dd];

__device__ h16 g_xh[Nn * Dd], g_xl[Nn * Dd];
__device__ h16 g_QKVh[24 * Nn * Dd], g_QKVl[8 * Nn * Dd];   // Q:0-7 K:8-15 V:16-23 (lo only for Q)
__device__ h16 g_Vth[(size_t)Hh * Dd * Nn];
__device__ h16 g_Sh[(size_t)Hh * Nn * Nn];                   // softmax probs, hi only
__device__ h16 g_mhh[(size_t)Nn * Hh * Dd], g_mhl[(size_t)Nn * Hh * Dd];
__device__ h16 g_h2h[Nn * Dd], g_h2l[Nn * Dd];
__device__ h16 g_ffh[Nn * Ff], g_ffl[Nn * Ff];
__device__ h16 g_Wh[24 * Dd * Dd];                            // QKV weights, hi only
__device__ h16 g_Woh[Dd * Hh * Dd];                           // Wo hi only (2-pass)
__device__ h16 g_W1h[Ff * Dd], g_W1l[Ff * Dd];
__device__ h16 g_W2h[Dd * Ff], g_W2l[Dd * Ff];

struct h2x2 { __half2 a, b; };

// ---------------- low-level helpers ----------------
__device__ __forceinline__ uint32_t smem_u32(const void* p) {
    uint32_t a;
    asm("{ .reg .u64 t; cvta.to.shared.u64 t, %1; cvt.u32.u64 %0, t; }" : "=r"(a) : "l"(p));
    return a;
}
__device__ __forceinline__ void ldm4(uint32_t* r, uint32_t addr) {
    asm volatile("ldmatrix.sync.aligned.m8n8.x4.shared.b16 {%0,%1,%2,%3}, [%4];"
                 : "=r"(r[0]), "=r"(r[1]), "=r"(r[2]), "=r"(r[3]) : "r"(addr));
}
__device__ __forceinline__ void mma16816(float* d, const uint32_t* a, const uint32_t* b) {
    asm volatile(
        "mma.sync.aligned.m16n8k16.row.col.f32.f16.f16.f32 "
        "{%0,%1,%2,%3}, {%4,%5,%6,%7}, {%8,%9}, {%0,%1,%2,%3};"
        : "+f"(d[0]), "+f"(d[1]), "+f"(d[2]), "+f"(d[3])
        : "r"(a[0]), "r"(a[1]), "r"(a[2]), "r"(a[3]), "r"(b[0]), "r"(b[1]));
}
__device__ __forceinline__ void cp16(uint32_t sdst, const void* gsrc) {
    asm volatile("cp.async.cg.shared.global [%0], [%1], 16;" :: "r"(sdst), "l"(gsrc));
}
#define CP_COMMIT() asm volatile("cp.async.commit_group;" ::: "memory")
#define CP_WAIT(n)  asm volatile("cp.async.wait_group %0;" :: "n"(n) : "memory")

// one 128x32 fp16 tile (row-major, leading dim ld) into 80B-pitched smem
__device__ __forceinline__ void cp_tile(uint32_t sdst, const h16* __restrict__ src,
                                        int ld, int row0, int k0, int tid) {
#pragma unroll
    for (int it = 0; it < 2; it++) {
        int idx = tid + it * 256;
        int r = idx >> 2, c = idx & 3;
        cp16(sdst + r * 80 + c * 16, src + (size_t)(row0 + r) * ld + k0 + c * 8);
    }
}

__device__ __forceinline__ void split_h(float v, h16* oh, h16* ol, size_t i) {
    h16 h = __float2half_rn(v);
    oh[i] = h;
    ol[i] = __float2half_rn(v - __half2float(h));
}

// ---------------- split-fp16 mma.sync GEMM: acc[M,N] = sum_k A[m,k]*B[n,k] ----------------
// CTA tile 128x128, 8 warps in 4(M)x2(N), 32x64 per warp.
// PASSES=1: Ah*Bh. PASSES=2: + Al*Bh. PASSES=3: + Ah*Bl.
// EPI: 0 = fp32 C (also split-K partials); 1 = (acc+bias) split fp16 (lo only if bz<loBz);
//      2 = gelu split.
template <int PASSES, int EPI, int MINB>
__global__ void __launch_bounds__(256, MINB)
gemm_h(const h16* __restrict__ Ah_, const h16* __restrict__ Al_,
       const h16* __restrict__ Bh_, const h16* __restrict__ Bl_,
       float* __restrict__ C, h16* __restrict__ Oh, h16* __restrict__ Ol,
       const float* __restrict__ bias,
       int K, int lda, int ldb, int ldc,
       long sA, long sB, long sC, long sBias, int loBz) {
    constexpr int NT = (PASSES == 1) ? 2 : ((PASSES == 2) ? 3 : 4);
    constexpr int STG = NT * 10240;
    constexpr int OAH = 0;
    constexpr int OAL = 10240;
    constexpr int OBH = (PASSES >= 2) ? 20480 : 10240;
    constexpr int OBL = 30720;
    extern __shared__ char smem[];
    const int tid = threadIdx.x;
    const int lane = tid & 31;
    const int wid = tid >> 5;
    const int wm = wid & 3;
    const int wn = wid >> 2;
    const int bz = blockIdx.z;
    const h16* Ahb = Ah_ + (size_t)bz * sA;
    const h16* Alb = (PASSES >= 2) ? Al_ + (size_t)bz * sA : nullptr;
    const h16* Bhb = Bh_ + (size_t)bz * sB;
    const h16* Blb = (PASSES == 3) ? Bl_ + (size_t)bz * sB : nullptr;
    const int m0 = blockIdx.y * 128;
    const int n0 = blockIdx.x * 128;
    const uint32_t sb = smem_u32(smem);

    float acc[2][8][4];
#pragma unroll
    for (int i = 0; i < 2; i++)
#pragma unroll
        for (int j = 0; j < 8; j++)
#pragma unroll
            for (int t = 0; t < 4; t++) acc[i][j][t] = 0.f;

    const int rowA = (lane & 15);
    const int colA = (lane >> 4) * 8;
    const int rowB = (lane & 7) + ((lane >> 4) & 1) * 8;
    const int colB = ((lane >> 3) & 1) * 8;

    const int nk = K >> 5;

    {
        cp_tile(sb + OAH, Ahb, lda, m0, 0, tid);
        if (PASSES >= 2) cp_tile(sb + OAL, Alb, lda, m0, 0, tid);
        cp_tile(sb + OBH, Bhb, ldb, n0, 0, tid);
        if (PASSES == 3) cp_tile(sb + OBL, Blb, ldb, n0, 0, tid);
        CP_COMMIT();
    }

    for (int kt = 0; kt < nk; kt++) {
        if (kt + 1 < nk) {
            uint32_t s1 = sb + ((kt + 1) & 1) * STG;
            int k0 = (kt + 1) << 5;
            cp_tile(s1 + OAH, Ahb, lda, m0, k0, tid);
            if (PASSES >= 2) cp_tile(s1 + OAL, Alb, lda, m0, k0, tid);
            cp_tile(s1 + OBH, Bhb, ldb, n0, k0, tid);
            if (PASSES == 3) cp_tile(s1 + OBL, Blb, ldb, n0, k0, tid);
            CP_COMMIT();
            CP_WAIT(1);
        } else {
            CP_WAIT(0);
        }
        __syncthreads();

        uint32_t s0 = sb + (kt & 1) * STG;
#pragma unroll
        for (int ks = 0; ks < 2; ks++) {
            uint32_t ah[2][4], al[2][4];
#pragma unroll
            for (int mi = 0; mi < 2; mi++) {
                uint32_t off = (uint32_t)((wm * 32 + mi * 16 + rowA) * 80 +
                                          (ks * 16 + colA) * 2);
                ldm4(ah[mi], s0 + OAH + off);
                if (PASSES >= 2) ldm4(al[mi], s0 + OAL + off);
            }
#pragma unroll
            for (int nj = 0; nj < 4; nj++) {
                uint32_t bh[4], bl[4];
                uint32_t off = (uint32_t)((wn * 64 + nj * 16 + rowB) * 80 +
                                          (ks * 16 + colB) * 2);
                ldm4(bh, s0 + OBH + off);
                if (PASSES == 3) ldm4(bl, s0 + OBL + off);
#pragma unroll
                for (int mi = 0; mi < 2; mi++)
#pragma unroll
                    for (int sub = 0; sub < 2; sub++) {
                        float* d = acc[mi][nj * 2 + sub];
                        mma16816(d, ah[mi], &bh[sub * 2]);
                        if (PASSES >= 2) mma16816(d, al[mi], &bh[sub * 2]);
                        if (PASSES == 3) mma16816(d, ah[mi], &bl[sub * 2]);
                    }
            }
        }
        __syncthreads();
    }

    // epilogue
    const bool wantLo = (EPI == 1) && (bz < loBz);
#pragma unroll
    for (int mi = 0; mi < 2; mi++) {
        int rbase = m0 + wm * 32 + mi * 16 + (lane >> 2);
#pragma unroll
        for (int nj = 0; nj < 8; nj++) {
            int c0 = n0 + wn * 64 + nj * 8 + (lane & 3) * 2;
            float* d = acc[mi][nj];
#pragma unroll
            for (int hr = 0; hr < 2; hr++) {
                int r = rbase + hr * 8;
                float v0 = d[hr * 2 + 0];
                float v1 = d[hr * 2 + 1];
                if (EPI == 0) {
                    *reinterpret_cast<float2*>(&C[(size_t)bz * sC + (size_t)r * ldc + c0]) =
                        make_float2(v0, v1);
                } else {
                    if (bias) {
                        v0 += bias[(size_t)bz * sBias + c0];
                        v1 += bias[(size_t)bz * sBias + c0 + 1];
                    }
                    if (EPI == 2) {
                        v0 = 0.5f * v0 * (1.0f + erff(v0 * 0.70710678118654752f));
                        v1 = 0.5f * v1 * (1.0f + erff(v1 * 0.70710678118654752f));
                    }
                    h16 h0 = __float2half_rn(v0), h1 = __float2half_rn(v1);
                    size_t o = (size_t)bz * sC + (size_t)r * ldc + c0;
                    *reinterpret_cast<__half2*>(&Oh[o]) = __halves2half2(h0, h1);
                    if (EPI == 2 || wantLo) {
                        *reinterpret_cast<__half2*>(&Ol[o]) = __halves2half2(
                            __float2half_rn(v0 - __half2float(h0)),
                            __float2half_rn(v1 - __half2float(h1)));
                    }
                }
            }
        }
    }
}

// ---------------- split-K reduce: out = p0 + p1 + bias + resid (fp32) ----------------
__global__ void reduce2_bias_resid(const float* __restrict__ p, const float* __restrict__ bias,
                                   const float* __restrict__ resid, float* __restrict__ out) {
    size_t i = (size_t)blockIdx.x * 256 + threadIdx.x;
    out[i] = p[i] + p[i + (size_t)Nn * Dd] + bias[i & (Dd - 1)] + resid[i];
}

// ---------------- weight prep: fp32 [R][C] -> fp16 [C][R] hi (+opt lo), scaled ----------------
__global__ void transpose_w(const float* __restrict__ in, h16* __restrict__ oh,
                            h16* __restrict__ ol, int R, int C, float scale) {
    __shared__ float t[32][33];
    int bz = blockIdx.z;
    size_t oz = (size_t)bz * R * C;
    int c0 = blockIdx.x * 32, r0 = blockIdx.y * 32;
    int tx = threadIdx.x, ty = threadIdx.y;  // (32,8)
#pragma unroll
    for (int k = 0; k < 4; k++) {
        int r = r0 + ty + k * 8;
        t[ty + k * 8][tx] = in[(size_t)bz * R * C + (size_t)r * C + c0 + tx] * scale;
    }
    __syncthreads();
#pragma unroll
    for (int k = 0; k < 4; k++) {
        int c = c0 + ty + k * 8;
        float v = t[tx][ty + k * 8];
        size_t i = oz + (size_t)c * R + r0 + tx;
        h16 h = __float2half_rn(v);
        oh[i] = h;
        if (ol) ol[i] = __float2half_rn(v - __half2float(h));
    }
}

// ---------------- V transpose: fp16 [N][D] -> [D][N] per batch ----------------
__global__ void transpose_h(const h16* __restrict__ in, h16* __restrict__ out, int R, int C) {
    __shared__ h16 t[32][33];
    int bz = blockIdx.z;
    const h16* inb = in + (size_t)bz * R * C;
    h16* ob = out + (size_t)bz * R * C;
    int c0 = blockIdx.x * 32, r0 = blockIdx.y * 32;
    int tx = threadIdx.x, ty = threadIdx.y;
#pragma unroll
    for (int k = 0; k < 4; k++) t[ty + k * 8][tx] = inb[(size_t)(r0 + ty + k * 8) * C + c0 + tx];
    __syncthreads();
#pragma unroll
    for (int k = 0; k < 4; k++)
        ob[(size_t)(c0 + ty + k * 8) * R + r0 + tx] = t[tx][ty + k * 8];
}

// ---------------- pack QKV biases (scale folded into Q) ----------------
__global__ void pack_bias(const float* __restrict__ bq, const float* __restrict__ bk,
                          const float* __restrict__ bv, float* __restrict__ o, float s) {
    int i = blockIdx.x * 256 + threadIdx.x;  // 24*512
    int z = i >> 9, c = i & 511;
    float v = (z < 8) ? bq[z * 512 + c] * s
                      : ((z < 16) ? bk[(z - 8) * 512 + c] : bv[(z - 16) * 512 + c]);
    o[i] = v;
}

// ---------------- layernorm(512) -> fp16 hi/lo ----------------
__global__ void layernorm512_split(const float* __restrict__ x, const float* __restrict__ g,
                                   const float* __restrict__ beta,
                                   h16* __restrict__ oh, h16* __restrict__ ol) {
    int row = blockIdx.x;
    const float* xr = x + (size_t)row * Dd;
    int tid = threadIdx.x;  // 128
    float v[4];
    float s = 0.f;
#pragma unroll
    for (int i = 0; i < 4; i++) { v[i] = xr[tid + i * 128]; s += v[i]; }
    __shared__ float red[4];
#pragma unroll
    for (int o = 16; o; o >>= 1) s += __shfl_xor_sync(0xffffffffu, s, o);
    if ((tid & 31) == 0) red[tid >> 5] = s;
    __syncthreads();
    float mu = (red[0] + red[1] + red[2] + red[3]) * (1.f / 512.f);
    float vs = 0.f;
#pragma unroll
    for (int i = 0; i < 4; i++) { float t = v[i] - mu; vs += t * t; }
#pragma unroll
    for (int o = 16; o; o >>= 1) vs += __shfl_xor_sync(0xffffffffu, vs, o);
    __syncthreads();
    if ((tid & 31) == 0) red[tid >> 5] = vs;
    __syncthreads();
    float var = (red[0] + red[1] + red[2] + red[3]) * (1.f / 512.f);
    float rstd = rsqrtf(var + 1e-5f);
#pragma unroll
    for (int i = 0; i < 4; i++) {
        int c = tid + i * 128;
        float o = (v[i] - mu) * rstd * g[c] + beta[c];
        split_h(o, oh, ol, (size_t)row * Dd + c);
    }
}

// ---------------- edge dot ----------------
__global__ void edge_d_kernel(const float* __restrict__ edge_attr,
                              const float* __restrict__ edge_vec,
                              float* __restrict__ dout) {
    __shared__ float ea[4][EDd];
    int e0 = blockIdx.x * 4;
    int tid = threadIdx.x;
    for (int i = tid; i < 4 * EDd; i += 128)
        ea[i >> 6][i & 63] = edge_attr[(size_t)e0 * EDd + i];
    __syncthreads();
    int el = tid >> 5;
    int hp = tid & 31;
    const float* ev = edge_vec + hp * EDd;
    float s = 0.f;
#pragma unroll
    for (int f = 0; f < EDd; f++) s += ea[el][f] * ev[f];
    int h = hp >> 2, p = hp & 3;
    dout[((size_t)h * Ee + (e0 + el)) * Pp + p] = s;
}

// ---------------- fused bias(b) + path-bias + softmax -> fp16 hi only (vectorized) ----------------
__global__ void bias_c_softmax(const float* __restrict__ S, const float* __restrict__ b,
                               const int* __restrict__ path_idx,
                               const int* __restrict__ path_len,
                               const float* __restrict__ dmat,
                               h16* __restrict__ Sh) {
    int h = blockIdx.x;
    int row = blockIdx.y;
    const float4* r4 = reinterpret_cast<const float4*>(S + ((size_t)h * Nn + row) * Nn);
    const float4* b4 = reinterpret_cast<const float4*>(b + (size_t)row * Nn);
    const int4* pl4 = reinterpret_cast<const int4*>(path_len + (size_t)row * Nn);
    const int4* pir = reinterpret_cast<const int4*>(path_idx + (size_t)row * Nn * Pp);
    const float* dh = dmat + (size_t)h * Ee * Pp;
    int tid = threadIdx.x;  // 256
    float v[8];
    float m = -1e30f;
#pragma unroll
    for (int i = 0; i < 2; i++) {
        int idx4 = tid + i * 256;
        float4 sv = r4[idx4];
        float4 bv = b4[idx4];
        int4 pl = pl4[idx4];
        float sarr[4] = {sv.x, sv.y, sv.z, sv.w};
        float barr[4] = {bv.x, bv.y, bv.z, bv.w};
        int plarr[4] = {pl.x, pl.y, pl.z, pl.w};
#pragma unroll
        for (int j = 0; j < 4; j++) {
            int pln = plarr[j];
            float c = 0.f;
            if (pln > 0) {
                const int4 pi = pir[idx4 * 4 + j];
                float s = dh[(size_t)pi.x * 4 + 0];
                if (1 < pln) s += dh[(size_t)pi.y * 4 + 1];
                if (2 < pln) s += dh[(size_t)pi.z * 4 + 2];
                if (3 < pln) s += dh[(size_t)pi.w * 4 + 3];
                c = s / (float)pln;
            }
            float val = sarr[j] + barr[j] + c;
            v[i * 4 + j] = val;
            m = fmaxf(m, val);
        }
    }
    __shared__ float red[8];
#pragma unroll
    for (int o = 16; o; o >>= 1) m = fmaxf(m, __shfl_xor_sync(0xffffffffu, m, o));
    if ((tid & 31) == 0) red[tid >> 5] = m;
    __syncthreads();
    m = red[0];
#pragma unroll
    for (int i = 1; i < 8; i++) m = fmaxf(m, red[i]);
    float s = 0.f;
#pragma unroll
    for (int i = 0; i < 8; i++) { v[i] = __expf(v[i] - m); s += v[i]; }
#pragma unroll
    for (int o = 16; o; o >>= 1) s += __shfl_xor_sync(0xffffffffu, s, o);
    __syncthreads();
    if ((tid & 31) == 0) red[tid >> 5] = s;
    __syncthreads();
    s = red[0];
#pragma unroll
    for (int i = 1; i < 8; i++) s += red[i];
    float inv = 1.f / s;
    h2x2* out2 = reinterpret_cast<h2x2*>(Sh + ((size_t)h * Nn + row) * Nn);
#pragma unroll
    for (int i = 0; i < 2; i++) {
        int idx4 = tid + i * 256;
        h2x2 pk;
        pk.a = __halves2half2(__float2half_rn(v[i * 4 + 0] * inv),
                              __float2half_rn(v[i * 4 + 1] * inv));
        pk.b = __halves2half2(__float2half_rn(v[i * 4 + 2] * inv),
                              __float2half_rn(v[i * 4 + 3] * inv));
        out2[idx4] = pk;
    }
}

// ---------------- host ----------------
#define GETSYM(var, sym) cudaGetSymbolAddress((void**)&var, sym)

extern "C" void kernel_launch(void* const* d_in, const int* in_sizes, int n_in,
                              void* d_out, int out_size) {
    const float* x         = (const float*)d_in[0];
    const float* edge_attr = (const float*)d_in[1];
    const float* b         = (const float*)d_in[2];
    const int*   path_idx  = (const int*)d_in[3];
    const int*   path_len  = (const int*)d_in[4];
    const float* Wq        = (const float*)d_in[5];
    const float* bq        = (const float*)d_in[6];
    const float* Wk        = (const float*)d_in[7];
    const float* bk        = (const float*)d_in[8];
    const float* Wv        = (const float*)d_in[9];
    const float* bv        = (const float*)d_in[10];
    const float* edge_vec  = (const float*)d_in[11];
    const float* Wo        = (const float*)d_in[12];
    const float* bo        = (const float*)d_in[13];
    const float* ln1_g     = (const float*)d_in[14];
    const float* ln1_b     = (const float*)d_in[15];
    const float* ln2_g     = (const float*)d_in[16];
    const float* ln2_b     = (const float*)d_in[17];
    const float* W1        = (const float*)d_in[18];
    const float* b1        = (const float*)d_in[19];
    const float* W2        = (const float*)d_in[20];
    const float* b2        = (const float*)d_in[21];
    float* out = (float*)d_out;

    float *Sf, *x1f, *dmat, *bqkv;
    GETSYM(Sf, g_Sf); GETSYM(x1f, g_x1); GETSYM(dmat, g_dmat); GETSYM(bqkv, g_bqkv);
    h16 *xh, *xl, *QKVh, *QKVl, *Vth, *Sh, *mhh, *mhl, *h2h, *h2l, *ffh, *ffl;
    h16 *Wh, *Woh, *W1h, *W1l, *W2h, *W2l;
    GETSYM(xh, g_xh); GETSYM(xl, g_xl);
    GETSYM(QKVh, g_QKVh); GETSYM(QKVl, g_QKVl);
    GETSYM(Vth, g_Vth);
    GETSYM(Sh, g_Sh);
    GETSYM(mhh, g_mhh); GETSYM(mhl, g_mhl);
    GETSYM(h2h, g_h2h); GETSYM(h2l, g_h2l);
    GETSYM(ffh, g_ffh); GETSYM(ffl, g_ffl);
    GETSYM(Wh, g_Wh);
    GETSYM(Woh, g_Woh);
    GETSYM(W1h, g_W1h); GETSYM(W1l, g_W1l);
    GETSYM(W2h, g_W2h); GETSYM(W2l, g_W2l);

    const int SM1 = 40960;
    const int SM2 = 61440;
    const int SM3 = 81920;
    cudaFuncSetAttribute(gemm_h<1, 1, 2>, cudaFuncAttributeMaxDynamicSharedMemorySize, SM1);
    cudaFuncSetAttribute(gemm_h<2, 0, 2>, cudaFuncAttributeMaxDynamicSharedMemorySize, SM2);
    cudaFuncSetAttribute(gemm_h<2, 1, 2>, cudaFuncAttributeMaxDynamicSharedMemorySize, SM2);
    cudaFuncSetAttribute(gemm_h<3, 2, 1>, cudaFuncAttributeMaxDynamicSharedMemorySize, SM3);
    cudaFuncSetAttribute(gemm_h<3, 0, 1>, cudaFuncAttributeMaxDynamicSharedMemorySize, SM3);

    const float scale = 1.0f / sqrtf((float)Dd);
    dim3 tb32(32, 8);
    const long ND = (long)Nn * Dd;
    const long NN = (long)Nn * Nn;

    // weight prep (transpose to K-major fp16)
    transpose_w<<<dim3(16, 16, Hh), tb32>>>(Wq, Wh, nullptr, Dd, Dd, scale);
    transpose_w<<<dim3(16, 16, Hh), tb32>>>(Wk, Wh + 8 * Dd * Dd, nullptr, Dd, Dd, 1.f);
    transpose_w<<<dim3(16, 16, Hh), tb32>>>(Wv, Wh + 16 * Dd * Dd, nullptr, Dd, Dd, 1.f);
    transpose_w<<<dim3(16, 128, 1), tb32>>>(Wo, Woh, nullptr, Hh * Dd, Dd, 1.f);
    transpose_w<<<dim3(64, 16, 1), tb32>>>(W1, W1h, W1l, Dd, Ff, 1.f);
    transpose_w<<<dim3(16, 64, 1), tb32>>>(W2, W2h, W2l, Ff, Dd, 1.f);
    pack_bias<<<48, 256>>>(bq, bk, bv, bqkv, scale);

    // LN1, edge dots
    layernorm512_split<<<Nn, 128>>>(x, ln1_g, ln1_b, xh, xl);
    edge_d_kernel<<<Ee / 4, 128>>>(edge_attr, edge_vec, dmat);

    // Q/K: batched 2-pass GEMM (16 batches), epilogue = +bias, split fp16 (lo only for Q)
    gemm_h<2, 1, 2><<<dim3(4, 16, 16), 256, SM2>>>(
        xh, xl, Wh, nullptr, nullptr, QKVh, QKVl, bqkv,
        Dd, Dd, Dd, Dd, 0, (long)Dd * Dd, ND, Dd, 8);

    // V: batched 1-pass GEMM (8 batches), hi out only
    gemm_h<1, 1, 2><<<dim3(4, 16, 8), 256, SM1>>>(
        xh, nullptr, Wh + 16 * (long)Dd * Dd, nullptr, nullptr,
        QKVh + 16 * ND, nullptr, bqkv + 16 * Dd,
        Dd, Dd, Dd, Dd, 0, (long)Dd * Dd, ND, Dd, 0);

    // V transpose (hi only) -> [H][D][N]
    transpose_h<<<dim3(16, 64, Hh), tb32>>>(QKVh + 16 * ND, Vth, Nn, Dd);

    // scores: S[h] = Qs @ K^T (2-pass, fp32 out)
    gemm_h<2, 0, 2><<<dim3(16, 16, Hh), 256, SM2>>>(
        QKVh, QKVl, QKVh + 8 * ND, nullptr, Sf, nullptr, nullptr, nullptr,
        Dd, Dd, Dd, Nn, ND, ND, NN, 0, 0);

    // spatial + path bias, softmax -> fp16 hi only
    bias_c_softmax<<<dim3(Hh, Nn), 256>>>(Sf, b, path_idx, path_len, dmat, Sh);

    // attn @ V -> mh (1-pass, split fp16 hi/lo out for Wo 2-pass)
    gemm_h<1, 1, 2><<<dim3(4, 16, Hh), 256, SM1>>>(
        Sh, nullptr, Vth, nullptr, nullptr, mhh, mhl, nullptr,
        Nn, Nn, Nn, Hh * Dd, NN, (long)Dd * Nn, Dd, 0, Hh);

    // x1 = mh @ Wo + bo + x  (2-pass, split-K=2 -> partials in Sf, then reduce)
    gemm_h<2, 0, 2><<<dim3(4, 16, 2), 256, SM2>>>(
        mhh, mhl, Woh, nullptr, Sf, nullptr, nullptr, nullptr,
        Hh * Dd / 2, Hh * Dd, Hh * Dd, Dd, Hh * Dd / 2, Hh * Dd / 2, ND, 0, 0);
    reduce2_bias_resid<<<(Nn * Dd) / 256, 256>>>(Sf, bo, x, x1f);

    // LN2
    layernorm512_split<<<Nn, 128>>>(x1f, ln2_g, ln2_b, h2h, h2l);

    // ff = gelu(h2 @ W1 + b1) (3-pass, fused gelu+split, MINB=1: no spills)
    gemm_h<3, 2, 1><<<dim3(16, 16, 1), 256, SM3>>>(
        h2h, h2l, W1h, W1l, nullptr, ffh, ffl, b1,
        Dd, Dd, Dd, Ff, 0, 0, 0, 0, 0);

    // out = ff @ W2 + b2 + x1 (3-pass, split-K=2 -> partials in Sf, then reduce)
    gemm_h<3, 0, 1><<<dim3(4, 16, 2), 256, SM3>>>(
        ffh, ffl, W2h, W2l, Sf, nullptr, nullptr, nullptr,
        Ff / 2, Ff, Ff, Dd, Ff / 2, Ff / 2, ND, 0, 0);
    reduce2_bias_resid<<<(Nn * Dd) / 256, 256>>>(Sf, b2, x1f, out);
}

// round 12
// speedup vs baseline: 1.0255x; 1.0255x over previous
#include <cuda_runtime.h>
#include <cuda_fp16.h>
#include <math.h>
#include <stdint.h>

#define Nn 2048
#define Dd 512
#define Hh 8
#define Ff 2048
#define EDd 64
#define Pp 4
#define Ee 32768

typedef __half h16;

// ---------------- static scratch (no allocations allowed) ----------------
__device__ float g_Sf[(size_t)Hh * Nn * Nn];      // 128 MB scores (+ split-K partials reuse)
__device__ float g_x1[Nn * Dd];
__device__ float g_dmat[Hh * Ee * Pp];
__device__ float g_bqkv[24 * Dd];

__device__ h16 g_xh[Nn * Dd], g_xl[Nn * Dd];
__device__ h16 g_QKVh[24 * Nn * Dd], g_QKVl[8 * Nn * Dd];   // Q:0-7 K:8-15 V:16-23 (lo only for Q)
__device__ h16 g_Vth[(size_t)Hh * Dd * Nn];
__device__ h16 g_Sh[(size_t)Hh * Nn * Nn];                   // softmax probs, hi only
__device__ h16 g_mhh[(size_t)Nn * Hh * Dd], g_mhl[(size_t)Nn * Hh * Dd];
__device__ h16 g_h2h[Nn * Dd], g_h2l[Nn * Dd];
__device__ h16 g_ffh[Nn * Ff], g_ffl[Nn * Ff];
__device__ h16 g_Wh[24 * Dd * Dd];                            // QKV weights, hi only
__device__ h16 g_Woh[Dd * Hh * Dd];                           // Wo hi only (2-pass)
__device__ h16 g_W1h[Ff * Dd], g_W1l[Ff * Dd];
__device__ h16 g_W2h[Dd * Ff], g_W2l[Dd * Ff];

struct h2x2 { __half2 a, b; };

// ---------------- low-level helpers ----------------
__device__ __forceinline__ uint32_t smem_u32(const void* p) {
    uint32_t a;
    asm("{ .reg .u64 t; cvta.to.shared.u64 t, %1; cvt.u32.u64 %0, t; }" : "=r"(a) : "l"(p));
    return a;
}
__device__ __forceinline__ void ldm4(uint32_t* r, uint32_t addr) {
    asm volatile("ldmatrix.sync.aligned.m8n8.x4.shared.b16 {%0,%1,%2,%3}, [%4];"
                 : "=r"(r[0]), "=r"(r[1]), "=r"(r[2]), "=r"(r[3]) : "r"(addr));
}
__device__ __forceinline__ void mma16816(float* d, const uint32_t* a, const uint32_t* b) {
    asm volatile(
        "mma.sync.aligned.m16n8k16.row.col.f32.f16.f16.f32 "
        "{%0,%1,%2,%3}, {%4,%5,%6,%7}, {%8,%9}, {%0,%1,%2,%3};"
        : "+f"(d[0]), "+f"(d[1]), "+f"(d[2]), "+f"(d[3])
        : "r"(a[0]), "r"(a[1]), "r"(a[2]), "r"(a[3]), "r"(b[0]), "r"(b[1]));
}
__device__ __forceinline__ void cp16(uint32_t sdst, const void* gsrc) {
    asm volatile("cp.async.cg.shared.global [%0], [%1], 16;" :: "r"(sdst), "l"(gsrc));
}
#define CP_COMMIT() asm volatile("cp.async.commit_group;" ::: "memory")
#define CP_WAIT(n)  asm volatile("cp.async.wait_group %0;" :: "n"(n) : "memory")

// one 128x32 fp16 tile (row-major, leading dim ld) into 80B-pitched smem
__device__ __forceinline__ void cp_tile(uint32_t sdst, const h16* __restrict__ src,
                                        int ld, int row0, int k0, int tid) {
#pragma unroll
    for (int it = 0; it < 2; it++) {
        int idx = tid + it * 256;
        int r = idx >> 2, c = idx & 3;
        cp16(sdst + r * 80 + c * 16, src + (size_t)(row0 + r) * ld + k0 + c * 8);
    }
}

__device__ __forceinline__ void split_h(float v, h16* oh, h16* ol, size_t i) {
    h16 h = __float2half_rn(v);
    oh[i] = h;
    ol[i] = __float2half_rn(v - __half2float(h));
}

// ---------------- split-fp16 mma.sync GEMM: acc[M,N] = sum_k A[m,k]*B[n,k] ----------------
// CTA tile 128x128, 8 warps in 4(M)x2(N), 32x64 per warp.
// PASSES=1: Ah*Bh. PASSES=2: + Al*Bh. PASSES=3: + Ah*Bl.
// Inner loop: preload ALL fragments (A and B) before the MMA block (R8 structure —
// lets ptxas batch LDSMs ahead of MMA issue; per-nj interleaving regressed in R10/R11).
// EPI: 0 = fp32 C (also split-K partials); 1 = (acc+bias) split fp16 (lo only if bz<loBz);
//      2 = gelu split.
template <int PASSES, int EPI, int MINB>
__global__ void __launch_bounds__(256, MINB)
gemm_h(const h16* __restrict__ Ah_, const h16* __restrict__ Al_,
       const h16* __restrict__ Bh_, const h16* __restrict__ Bl_,
       float* __restrict__ C, h16* __restrict__ Oh, h16* __restrict__ Ol,
       const float* __restrict__ bias,
       int K, int lda, int ldb, int ldc,
       long sA, long sB, long sC, long sBias, int loBz) {
    constexpr int NT = (PASSES == 1) ? 2 : ((PASSES == 2) ? 3 : 4);
    constexpr int STG = NT * 10240;
    constexpr int OAH = 0;
    constexpr int OAL = 10240;
    constexpr int OBH = (PASSES >= 2) ? 20480 : 10240;
    constexpr int OBL = 30720;
    extern __shared__ char smem[];
    const int tid = threadIdx.x;
    const int lane = tid & 31;
    const int wid = tid >> 5;
    const int wm = wid & 3;
    const int wn = wid >> 2;
    const int bz = blockIdx.z;
    const h16* Ahb = Ah_ + (size_t)bz * sA;
    const h16* Alb = (PASSES >= 2) ? Al_ + (size_t)bz * sA : nullptr;
    const h16* Bhb = Bh_ + (size_t)bz * sB;
    const h16* Blb = (PASSES == 3) ? Bl_ + (size_t)bz * sB : nullptr;
    const int m0 = blockIdx.y * 128;
    const int n0 = blockIdx.x * 128;
    const uint32_t sb = smem_u32(smem);

    float acc[2][8][4];
#pragma unroll
    for (int i = 0; i < 2; i++)
#pragma unroll
        for (int j = 0; j < 8; j++)
#pragma unroll
            for (int t = 0; t < 4; t++) acc[i][j][t] = 0.f;

    const int rowA = (lane & 15);
    const int colA = (lane >> 4) * 8;
    const int rowB = (lane & 7) + ((lane >> 4) & 1) * 8;
    const int colB = ((lane >> 3) & 1) * 8;

    const int nk = K >> 5;

    {
        cp_tile(sb + OAH, Ahb, lda, m0, 0, tid);
        if (PASSES >= 2) cp_tile(sb + OAL, Alb, lda, m0, 0, tid);
        cp_tile(sb + OBH, Bhb, ldb, n0, 0, tid);
        if (PASSES == 3) cp_tile(sb + OBL, Blb, ldb, n0, 0, tid);
        CP_COMMIT();
    }

    for (int kt = 0; kt < nk; kt++) {
        if (kt + 1 < nk) {
            uint32_t s1 = sb + ((kt + 1) & 1) * STG;
            int k0 = (kt + 1) << 5;
            cp_tile(s1 + OAH, Ahb, lda, m0, k0, tid);
            if (PASSES >= 2) cp_tile(s1 + OAL, Alb, lda, m0, k0, tid);
            cp_tile(s1 + OBH, Bhb, ldb, n0, k0, tid);
            if (PASSES == 3) cp_tile(s1 + OBL, Blb, ldb, n0, k0, tid);
            CP_COMMIT();
            CP_WAIT(1);
        } else {
            CP_WAIT(0);
        }
        __syncthreads();

        uint32_t s0 = sb + (kt & 1) * STG;
#pragma unroll
        for (int ks = 0; ks < 2; ks++) {
            uint32_t ah[2][4], al[2][4], bh[4][4], bl[4][4];
#pragma unroll
            for (int mi = 0; mi < 2; mi++) {
                uint32_t off = (uint32_t)((wm * 32 + mi * 16 + rowA) * 80 +
                                          (ks * 16 + colA) * 2);
                ldm4(ah[mi], s0 + OAH + off);
                if (PASSES >= 2) ldm4(al[mi], s0 + OAL + off);
            }
#pragma unroll
            for (int nj = 0; nj < 4; nj++) {
                uint32_t off = (uint32_t)((wn * 64 + nj * 16 + rowB) * 80 +
                                          (ks * 16 + colB) * 2);
                ldm4(bh[nj], s0 + OBH + off);
                if (PASSES == 3) ldm4(bl[nj], s0 + OBL + off);
            }
#pragma unroll
            for (int mi = 0; mi < 2; mi++)
#pragma unroll
                for (int nj = 0; nj < 4; nj++)
#pragma unroll
                    for (int sub = 0; sub < 2; sub++) {
                        float* d = acc[mi][nj * 2 + sub];
                        mma16816(d, ah[mi], &bh[nj][sub * 2]);
                        if (PASSES >= 2) mma16816(d, al[mi], &bh[nj][sub * 2]);
                        if (PASSES == 3) mma16816(d, ah[mi], &bl[nj][sub * 2]);
                    }
        }
        __syncthreads();
    }

    // epilogue
    const bool wantLo = (EPI == 1) && (bz < loBz);
#pragma unroll
    for (int mi = 0; mi < 2; mi++) {
        int rbase = m0 + wm * 32 + mi * 16 + (lane >> 2);
#pragma unroll
        for (int nj = 0; nj < 8; nj++) {
            int c0 = n0 + wn * 64 + nj * 8 + (lane & 3) * 2;
            float* d = acc[mi][nj];
#pragma unroll
            for (int hr = 0; hr < 2; hr++) {
                int r = rbase + hr * 8;
                float v0 = d[hr * 2 + 0];
                float v1 = d[hr * 2 + 1];
                if (EPI == 0) {
                    *reinterpret_cast<float2*>(&C[(size_t)bz * sC + (size_t)r * ldc + c0]) =
                        make_float2(v0, v1);
                } else {
                    if (bias) {
                        v0 += bias[(size_t)bz * sBias + c0];
                        v1 += bias[(size_t)bz * sBias + c0 + 1];
                    }
                    if (EPI == 2) {
                        v0 = 0.5f * v0 * (1.0f + erff(v0 * 0.70710678118654752f));
                        v1 = 0.5f * v1 * (1.0f + erff(v1 * 0.70710678118654752f));
                    }
                    h16 h0 = __float2half_rn(v0), h1 = __float2half_rn(v1);
                    size_t o = (size_t)bz * sC + (size_t)r * ldc + c0;
                    *reinterpret_cast<__half2*>(&Oh[o]) = __halves2half2(h0, h1);
                    if (EPI == 2 || wantLo) {
                        *reinterpret_cast<__half2*>(&Ol[o]) = __halves2half2(
                            __float2half_rn(v0 - __half2float(h0)),
                            __float2half_rn(v1 - __half2float(h1)));
                    }
                }
            }
        }
    }
}

// ---------------- split-K reduce: out = p0 + p1 + bias + resid (fp32) ----------------
__global__ void reduce2_bias_resid(const float* __restrict__ p, const float* __restrict__ bias,
                                   const float* __restrict__ resid, float* __restrict__ out) {
    size_t i = (size_t)blockIdx.x * 256 + threadIdx.x;
    out[i] = p[i] + p[i + (size_t)Nn * Dd] + bias[i & (Dd - 1)] + resid[i];
}

// ---------------- weight prep: fp32 [R][C] -> fp16 [C][R] hi (+opt lo), scaled ----------------
__global__ void transpose_w(const float* __restrict__ in, h16* __restrict__ oh,
                            h16* __restrict__ ol, int R, int C, float scale) {
    __shared__ float t[32][33];
    int bz = blockIdx.z;
    size_t oz = (size_t)bz * R * C;
    int c0 = blockIdx.x * 32, r0 = blockIdx.y * 32;
    int tx = threadIdx.x, ty = threadIdx.y;  // (32,8)
#pragma unroll
    for (int k = 0; k < 4; k++) {
        int r = r0 + ty + k * 8;
        t[ty + k * 8][tx] = in[(size_t)bz * R * C + (size_t)r * C + c0 + tx] * scale;
    }
    __syncthreads();
#pragma unroll
    for (int k = 0; k < 4; k++) {
        int c = c0 + ty + k * 8;
        float v = t[tx][ty + k * 8];
        size_t i = oz + (size_t)c * R + r0 + tx;
        h16 h = __float2half_rn(v);
        oh[i] = h;
        if (ol) ol[i] = __float2half_rn(v - __half2float(h));
    }
}

// ---------------- V transpose: fp16 [N][D] -> [D][N] per batch ----------------
__global__ void transpose_h(const h16* __restrict__ in, h16* __restrict__ out, int R, int C) {
    __shared__ h16 t[32][33];
    int bz = blockIdx.z;
    const h16* inb = in + (size_t)bz * R * C;
    h16* ob = out + (size_t)bz * R * C;
    int c0 = blockIdx.x * 32, r0 = blockIdx.y * 32;
    int tx = threadIdx.x, ty = threadIdx.y;
#pragma unroll
    for (int k = 0; k < 4; k++) t[ty + k * 8][tx] = inb[(size_t)(r0 + ty + k * 8) * C + c0 + tx];
    __syncthreads();
#pragma unroll
    for (int k = 0; k < 4; k++)
        ob[(size_t)(c0 + ty + k * 8) * R + r0 + tx] = t[tx][ty + k * 8];
}

// ---------------- pack QKV biases (scale folded into Q) ----------------
__global__ void pack_bias(const float* __restrict__ bq, const float* __restrict__ bk,
                          const float* __restrict__ bv, float* __restrict__ o, float s) {
    int i = blockIdx.x * 256 + threadIdx.x;  // 24*512
    int z = i >> 9, c = i & 511;
    float v = (z < 8) ? bq[z * 512 + c] * s
                      : ((z < 16) ? bk[(z - 8) * 512 + c] : bv[(z - 16) * 512 + c]);
    o[i] = v;
}

// ---------------- layernorm(512) -> fp16 hi/lo ----------------
__global__ void layernorm512_split(const float* __restrict__ x, const float* __restrict__ g,
                                   const float* __restrict__ beta,
                                   h16* __restrict__ oh, h16* __restrict__ ol) {
    int row = blockIdx.x;
    const float* xr = x + (size_t)row * Dd;
    int tid = threadIdx.x;  // 128
    float v[4];
    float s = 0.f;
#pragma unroll
    for (int i = 0; i < 4; i++) { v[i] = xr[tid + i * 128]; s += v[i]; }
    __shared__ float red[4];
#pragma unroll
    for (int o = 16; o; o >>= 1) s += __shfl_xor_sync(0xffffffffu, s, o);
    if ((tid & 31) == 0) red[tid >> 5] = s;
    __syncthreads();
    float mu = (red[0] + red[1] + red[2] + red[3]) * (1.f / 512.f);
    float vs = 0.f;
#pragma unroll
    for (int i = 0; i < 4; i++) { float t = v[i] - mu; vs += t * t; }
#pragma unroll
    for (int o = 16; o; o >>= 1) vs += __shfl_xor_sync(0xffffffffu, vs, o);
    __syncthreads();
    if ((tid & 31) == 0) red[tid >> 5] = vs;
    __syncthreads();
    float var = (red[0] + red[1] + red[2] + red[3]) * (1.f / 512.f);
    float rstd = rsqrtf(var + 1e-5f);
#pragma unroll
    for (int i = 0; i < 4; i++) {
        int c = tid + i * 128;
        float o = (v[i] - mu) * rstd * g[c] + beta[c];
        split_h(o, oh, ol, (size_t)row * Dd + c);
    }
}

// ---------------- edge dot ----------------
__global__ void edge_d_kernel(const float* __restrict__ edge_attr,
                              const float* __restrict__ edge_vec,
                              float* __restrict__ dout) {
    __shared__ float ea[4][EDd];
    int e0 = blockIdx.x * 4;
    int tid = threadIdx.x;
    for (int i = tid; i < 4 * EDd; i += 128)
        ea[i >> 6][i & 63] = edge_attr[(size_t)e0 * EDd + i];
    __syncthreads();
    int el = tid >> 5;
    int hp = tid & 31;
    const float* ev = edge_vec + hp * EDd;
    float s = 0.f;
#pragma unroll
    for (int f = 0; f < EDd; f++) s += ea[el][f] * ev[f];
    int h = hp >> 2, p = hp & 3;
    dout[((size_t)h * Ee + (e0 + el)) * Pp + p] = s;
}

// ---------------- fused bias(b) + path-bias + softmax -> fp16 hi only (vectorized) ----------------
__global__ void bias_c_softmax(const float* __restrict__ S, const float* __restrict__ b,
                               const int* __restrict__ path_idx,
                               const int* __restrict__ path_len,
                               const float* __restrict__ dmat,
                               h16* __restrict__ Sh) {
    int h = blockIdx.x;
    int row = blockIdx.y;
    const float4* r4 = reinterpret_cast<const float4*>(S + ((size_t)h * Nn + row) * Nn);
    const float4* b4 = reinterpret_cast<const float4*>(b + (size_t)row * Nn);
    const int4* pl4 = reinterpret_cast<const int4*>(path_len + (size_t)row * Nn);
    const int4* pir = reinterpret_cast<const int4*>(path_idx + (size_t)row * Nn * Pp);
    const float* dh = dmat + (size_t)h * Ee * Pp;
    int tid = threadIdx.x;  // 256
    float v[8];
    float m = -1e30f;
#pragma unroll
    for (int i = 0; i < 2; i++) {
        int idx4 = tid + i * 256;
        float4 sv = r4[idx4];
        float4 bv = b4[idx4];
        int4 pl = pl4[idx4];
        float sarr[4] = {sv.x, sv.y, sv.z, sv.w};
        float barr[4] = {bv.x, bv.y, bv.z, bv.w};
        int plarr[4] = {pl.x, pl.y, pl.z, pl.w};
#pragma unroll
        for (int j = 0; j < 4; j++) {
            int pln = plarr[j];
            float c = 0.f;
            if (pln > 0) {
                const int4 pi = pir[idx4 * 4 + j];
                float s = dh[(size_t)pi.x * 4 + 0];
                if (1 < pln) s += dh[(size_t)pi.y * 4 + 1];
                if (2 < pln) s += dh[(size_t)pi.z * 4 + 2];
                if (3 < pln) s += dh[(size_t)pi.w * 4 + 3];
                c = s / (float)pln;
            }
            float val = sarr[j] + barr[j] + c;
            v[i * 4 + j] = val;
            m = fmaxf(m, val);
        }
    }
    __shared__ float red[8];
#pragma unroll
    for (int o = 16; o; o >>= 1) m = fmaxf(m, __shfl_xor_sync(0xffffffffu, m, o));
    if ((tid & 31) == 0) red[tid >> 5] = m;
    __syncthreads();
    m = red[0];
#pragma unroll
    for (int i = 1; i < 8; i++) m = fmaxf(m, red[i]);
    float s = 0.f;
#pragma unroll
    for (int i = 0; i < 8; i++) { v[i] = __expf(v[i] - m); s += v[i]; }
#pragma unroll
    for (int o = 16; o; o >>= 1) s += __shfl_xor_sync(0xffffffffu, s, o);
    __syncthreads();
    if ((tid & 31) == 0) red[tid >> 5] = s;
    __syncthreads();
    s = red[0];
#pragma unroll
    for (int i = 1; i < 8; i++) s += red[i];
    float inv = 1.f / s;
    h2x2* out2 = reinterpret_cast<h2x2*>(Sh + ((size_t)h * Nn + row) * Nn);
#pragma unroll
    for (int i = 0; i < 2; i++) {
        int idx4 = tid + i * 256;
        h2x2 pk;
        pk.a = __halves2half2(__float2half_rn(v[i * 4 + 0] * inv),
                              __float2half_rn(v[i * 4 + 1] * inv));
        pk.b = __halves2half2(__float2half_rn(v[i * 4 + 2] * inv),
                              __float2half_rn(v[i * 4 + 3] * inv));
        out2[idx4] = pk;
    }
}

// ---------------- host ----------------
#define GETSYM(var, sym) cudaGetSymbolAddress((void**)&var, sym)

extern "C" void kernel_launch(void* const* d_in, const int* in_sizes, int n_in,
                              void* d_out, int out_size) {
    const float* x         = (const float*)d_in[0];
    const float* edge_attr = (const float*)d_in[1];
    const float* b         = (const float*)d_in[2];
    const int*   path_idx  = (const int*)d_in[3];
    const int*   path_len  = (const int*)d_in[4];
    const float* Wq        = (const float*)d_in[5];
    const float* bq        = (const float*)d_in[6];
    const float* Wk        = (const float*)d_in[7];
    const float* bk        = (const float*)d_in[8];
    const float* Wv        = (const float*)d_in[9];
    const float* bv        = (const float*)d_in[10];
    const float* edge_vec  = (const float*)d_in[11];
    const float* Wo        = (const float*)d_in[12];
    const float* bo        = (const float*)d_in[13];
    const float* ln1_g     = (const float*)d_in[14];
    const float* ln1_b     = (const float*)d_in[15];
    const float* ln2_g     = (const float*)d_in[16];
    const float* ln2_b     = (const float*)d_in[17];
    const float* W1        = (const float*)d_in[18];
    const float* b1        = (const float*)d_in[19];
    const float* W2        = (const float*)d_in[20];
    const float* b2        = (const float*)d_in[21];
    float* out = (float*)d_out;

    float *Sf, *x1f, *dmat, *bqkv;
    GETSYM(Sf, g_Sf); GETSYM(x1f, g_x1); GETSYM(dmat, g_dmat); GETSYM(bqkv, g_bqkv);
    h16 *xh, *xl, *QKVh, *QKVl, *Vth, *Sh, *mhh, *mhl, *h2h, *h2l, *ffh, *ffl;
    h16 *Wh, *Woh, *W1h, *W1l, *W2h, *W2l;
    GETSYM(xh, g_xh); GETSYM(xl, g_xl);
    GETSYM(QKVh, g_QKVh); GETSYM(QKVl, g_QKVl);
    GETSYM(Vth, g_Vth);
    GETSYM(Sh, g_Sh);
    GETSYM(mhh, g_mhh); GETSYM(mhl, g_mhl);
    GETSYM(h2h, g_h2h); GETSYM(h2l, g_h2l);
    GETSYM(ffh, g_ffh); GETSYM(ffl, g_ffl);
    GETSYM(Wh, g_Wh);
    GETSYM(Woh, g_Woh);
    GETSYM(W1h, g_W1h); GETSYM(W1l, g_W1l);
    GETSYM(W2h, g_W2h); GETSYM(W2l, g_W2l);

    const int SM1 = 40960;
    const int SM2 = 61440;
    const int SM3 = 81920;
    cudaFuncSetAttribute(gemm_h<1, 1, 2>, cudaFuncAttributeMaxDynamicSharedMemorySize, SM1);
    cudaFuncSetAttribute(gemm_h<2, 0, 2>, cudaFuncAttributeMaxDynamicSharedMemorySize, SM2);
    cudaFuncSetAttribute(gemm_h<2, 1, 2>, cudaFuncAttributeMaxDynamicSharedMemorySize, SM2);
    cudaFuncSetAttribute(gemm_h<3, 2, 1>, cudaFuncAttributeMaxDynamicSharedMemorySize, SM3);
    cudaFuncSetAttribute(gemm_h<3, 0, 1>, cudaFuncAttributeMaxDynamicSharedMemorySize, SM3);

    const float scale = 1.0f / sqrtf((float)Dd);
    dim3 tb32(32, 8);
    const long ND = (long)Nn * Dd;
    const long NN = (long)Nn * Nn;

    // weight prep (transpose to K-major fp16)
    transpose_w<<<dim3(16, 16, Hh), tb32>>>(Wq, Wh, nullptr, Dd, Dd, scale);
    transpose_w<<<dim3(16, 16, Hh), tb32>>>(Wk, Wh + 8 * Dd * Dd, nullptr, Dd, Dd, 1.f);
    transpose_w<<<dim3(16, 16, Hh), tb32>>>(Wv, Wh + 16 * Dd * Dd, nullptr, Dd, Dd, 1.f);
    transpose_w<<<dim3(16, 128, 1), tb32>>>(Wo, Woh, nullptr, Hh * Dd, Dd, 1.f);
    transpose_w<<<dim3(64, 16, 1), tb32>>>(W1, W1h, W1l, Dd, Ff, 1.f);
    transpose_w<<<dim3(16, 64, 1), tb32>>>(W2, W2h, W2l, Ff, Dd, 1.f);
    pack_bias<<<48, 256>>>(bq, bk, bv, bqkv, scale);

    // LN1, edge dots
    layernorm512_split<<<Nn, 128>>>(x, ln1_g, ln1_b, xh, xl);
    edge_d_kernel<<<Ee / 4, 128>>>(edge_attr, edge_vec, dmat);

    // Q/K: batched 2-pass GEMM (16 batches), epilogue = +bias, split fp16 (lo only for Q)
    gemm_h<2, 1, 2><<<dim3(4, 16, 16), 256, SM2>>>(
        xh, xl, Wh, nullptr, nullptr, QKVh, QKVl, bqkv,
        Dd, Dd, Dd, Dd, 0, (long)Dd * Dd, ND, Dd, 8);

    // V: batched 1-pass GEMM (8 batches), hi out only
    gemm_h<1, 1, 2><<<dim3(4, 16, 8), 256, SM1>>>(
        xh, nullptr, Wh + 16 * (long)Dd * Dd, nullptr, nullptr,
        QKVh + 16 * ND, nullptr, bqkv + 16 * Dd,
        Dd, Dd, Dd, Dd, 0, (long)Dd * Dd, ND, Dd, 0);

    // V transpose (hi only) -> [H][D][N]
    transpose_h<<<dim3(16, 64, Hh), tb32>>>(QKVh + 16 * ND, Vth, Nn, Dd);

    // scores: S[h] = Qs @ K^T (2-pass, fp32 out)
    gemm_h<2, 0, 2><<<dim3(16, 16, Hh), 256, SM2>>>(
        QKVh, QKVl, QKVh + 8 * ND, nullptr, Sf, nullptr, nullptr, nullptr,
        Dd, Dd, Dd, Nn, ND, ND, NN, 0, 0);

    // spatial + path bias, softmax -> fp16 hi only
    bias_c_softmax<<<dim3(Hh, Nn), 256>>>(Sf, b, path_idx, path_len, dmat, Sh);

    // attn @ V -> mh (1-pass, split fp16 hi/lo out for Wo 2-pass)
    gemm_h<1, 1, 2><<<dim3(4, 16, Hh), 256, SM1>>>(
        Sh, nullptr, Vth, nullptr, nullptr, mhh, mhl, nullptr,
        Nn, Nn, Nn, Hh * Dd, NN, (long)Dd * Nn, Dd, 0, Hh);

    // x1 = mh @ Wo + bo + x  (2-pass, split-K=2 -> partials in Sf, then reduce)
    gemm_h<2, 0, 2><<<dim3(4, 16, 2), 256, SM2>>>(
        mhh, mhl, Woh, nullptr, Sf, nullptr, nullptr, nullptr,
        Hh * Dd / 2, Hh * Dd, Hh * Dd, Dd, Hh * Dd / 2, Hh * Dd / 2, ND, 0, 0);
    reduce2_bias_resid<<<(Nn * Dd) / 256, 256>>>(Sf, bo, x, x1f);

    // LN2
    layernorm512_split<<<Nn, 128>>>(x1f, ln2_g, ln2_b, h2h, h2l);

    // ff = gelu(h2 @ W1 + b1) (3-pass, fused gelu+split)
    gemm_h<3, 2, 1><<<dim3(16, 16, 1), 256, SM3>>>(
        h2h, h2l, W1h, W1l, nullptr, ffh, ffl, b1,
        Dd, Dd, Dd, Ff, 0, 0, 0, 0, 0);

    // out = ff @ W2 + b2 + x1 (3-pass, split-K=2 -> partials in Sf, then reduce)
    gemm_h<3, 0, 1><<<dim3(4, 16, 2), 256, SM3>>>(
        ffh, ffl, W2h, W2l, Sf, nullptr, nullptr, nullptr,
        Ff / 2, Ff, Ff, Dd, Ff / 2, Ff / 2, ND, 0, 0);
    reduce2_bias_resid<<<(Nn * Dd) / 256, 256>>>(Sf, b2, x1f, out);
}

// round 13
// speedup vs baseline: 1.0296x; 1.0040x over previous
#include <cuda_runtime.h>
#include <cuda_fp16.h>
#include <math.h>
#include <stdint.h>

#define Nn 2048
#define Dd 512
#define Hh 8
#define Ff 2048
#define EDd 64
#define Pp 4
#define Ee 32768

typedef __half h16;

// ---------------- static scratch (no allocations allowed) ----------------
__device__ float g_Sf[(size_t)Hh * Nn * Nn];      // 128 MB scores (+ split-K partials reuse)
__device__ float g_x1[Nn * Dd];
__device__ float g_dmat[Hh * Ee * Pp];
__device__ float g_bqkv[24 * Dd];

__device__ h16 g_xh[Nn * Dd], g_xl[Nn * Dd];
__device__ h16 g_QKVh[16 * Nn * Dd], g_QKVl[8 * Nn * Dd];   // Q:0-7 K:8-15 (lo only for Q)
__device__ h16 g_Vth[(size_t)Hh * Dd * Nn];                  // V^T computed directly
__device__ h16 g_Sh[(size_t)Hh * Nn * Nn];                   // softmax probs, hi only
__device__ h16 g_mhh[(size_t)Nn * Hh * Dd], g_mhl[(size_t)Nn * Hh * Dd];
__device__ h16 g_h2h[Nn * Dd], g_h2l[Nn * Dd];
__device__ h16 g_ffh[Nn * Ff], g_ffl[Nn * Ff];
__device__ h16 g_Wh[24 * Dd * Dd];                            // QKV weights (transposed), hi only
__device__ h16 g_Woh[Dd * Hh * Dd];                           // Wo hi only (2-pass)
__device__ h16 g_W1h[Ff * Dd], g_W1l[Ff * Dd];
__device__ h16 g_W2h[Dd * Ff], g_W2l[Dd * Ff];

struct h2x2 { __half2 a, b; };

// ---------------- low-level helpers ----------------
__device__ __forceinline__ uint32_t smem_u32(const void* p) {
    uint32_t a;
    asm("{ .reg .u64 t; cvta.to.shared.u64 t, %1; cvt.u32.u64 %0, t; }" : "=r"(a) : "l"(p));
    return a;
}
__device__ __forceinline__ void ldm4(uint32_t* r, uint32_t addr) {
    asm volatile("ldmatrix.sync.aligned.m8n8.x4.shared.b16 {%0,%1,%2,%3}, [%4];"
                 : "=r"(r[0]), "=r"(r[1]), "=r"(r[2]), "=r"(r[3]) : "r"(addr));
}
__device__ __forceinline__ void mma16816(float* d, const uint32_t* a, const uint32_t* b) {
    asm volatile(
        "mma.sync.aligned.m16n8k16.row.col.f32.f16.f16.f32 "
        "{%0,%1,%2,%3}, {%4,%5,%6,%7}, {%8,%9}, {%0,%1,%2,%3};"
        : "+f"(d[0]), "+f"(d[1]), "+f"(d[2]), "+f"(d[3])
        : "r"(a[0]), "r"(a[1]), "r"(a[2]), "r"(a[3]), "r"(b[0]), "r"(b[1]));
}
__device__ __forceinline__ void cp16(uint32_t sdst, const void* gsrc) {
    asm volatile("cp.async.cg.shared.global [%0], [%1], 16;" :: "r"(sdst), "l"(gsrc));
}
#define CP_COMMIT() asm volatile("cp.async.commit_group;" ::: "memory")
#define CP_WAIT(n)  asm volatile("cp.async.wait_group %0;" :: "n"(n) : "memory")

// one 128x32 fp16 tile (row-major, leading dim ld) into 80B-pitched smem
__device__ __forceinline__ void cp_tile(uint32_t sdst, const h16* __restrict__ src,
                                        int ld, int row0, int k0, int tid) {
#pragma unroll
    for (int it = 0; it < 2; it++) {
        int idx = tid + it * 256;
        int r = idx >> 2, c = idx & 3;
        cp16(sdst + r * 80 + c * 16, src + (size_t)(row0 + r) * ld + k0 + c * 8);
    }
}

__device__ __forceinline__ void split_h(float v, h16* oh, h16* ol, size_t i) {
    h16 h = __float2half_rn(v);
    oh[i] = h;
    ol[i] = __float2half_rn(v - __half2float(h));
}

// ---------------- split-fp16 mma.sync GEMM: acc[M,N] = sum_k A[m,k]*B[n,k] ----------------
// CTA tile 128x128, 8 warps in 4(M)x2(N), 32x64 per warp.
// PASSES=1: Ah*Bh. PASSES=2: + Al*Bh. PASSES=3: + Ah*Bl.
// Inner loop: preload ALL fragments before the MMA block (R8 structure).
// EPI: 0 = fp32 C (also split-K partials); 1 = (acc + colbias) split fp16 (lo only if bz<loBz);
//      2 = gelu split; 3 = (acc + rowbias[m]) fp16 hi only.
template <int PASSES, int EPI, int MINB>
__global__ void __launch_bounds__(256, MINB)
gemm_h(const h16* __restrict__ Ah_, const h16* __restrict__ Al_,
       const h16* __restrict__ Bh_, const h16* __restrict__ Bl_,
       float* __restrict__ C, h16* __restrict__ Oh, h16* __restrict__ Ol,
       const float* __restrict__ bias,
       int K, int lda, int ldb, int ldc,
       long sA, long sB, long sC, long sBias, int loBz) {
    constexpr int NT = (PASSES == 1) ? 2 : ((PASSES == 2) ? 3 : 4);
    constexpr int STG = NT * 10240;
    constexpr int OAH = 0;
    constexpr int OAL = 10240;
    constexpr int OBH = (PASSES >= 2) ? 20480 : 10240;
    constexpr int OBL = 30720;
    extern __shared__ char smem[];
    const int tid = threadIdx.x;
    const int lane = tid & 31;
    const int wid = tid >> 5;
    const int wm = wid & 3;
    const int wn = wid >> 2;
    const int bz = blockIdx.z;
    const h16* Ahb = Ah_ + (size_t)bz * sA;
    const h16* Alb = (PASSES >= 2) ? Al_ + (size_t)bz * sA : nullptr;
    const h16* Bhb = Bh_ + (size_t)bz * sB;
    const h16* Blb = (PASSES == 3) ? Bl_ + (size_t)bz * sB : nullptr;
    const int m0 = blockIdx.y * 128;
    const int n0 = blockIdx.x * 128;
    const uint32_t sb = smem_u32(smem);

    float acc[2][8][4];
#pragma unroll
    for (int i = 0; i < 2; i++)
#pragma unroll
        for (int j = 0; j < 8; j++)
#pragma unroll
            for (int t = 0; t < 4; t++) acc[i][j][t] = 0.f;

    const int rowA = (lane & 15);
    const int colA = (lane >> 4) * 8;
    const int rowB = (lane & 7) + ((lane >> 4) & 1) * 8;
    const int colB = ((lane >> 3) & 1) * 8;

    const int nk = K >> 5;

    {
        cp_tile(sb + OAH, Ahb, lda, m0, 0, tid);
        if (PASSES >= 2) cp_tile(sb + OAL, Alb, lda, m0, 0, tid);
        cp_tile(sb + OBH, Bhb, ldb, n0, 0, tid);
        if (PASSES == 3) cp_tile(sb + OBL, Blb, ldb, n0, 0, tid);
        CP_COMMIT();
    }

    for (int kt = 0; kt < nk; kt++) {
        if (kt + 1 < nk) {
            uint32_t s1 = sb + ((kt + 1) & 1) * STG;
            int k0 = (kt + 1) << 5;
            cp_tile(s1 + OAH, Ahb, lda, m0, k0, tid);
            if (PASSES >= 2) cp_tile(s1 + OAL, Alb, lda, m0, k0, tid);
            cp_tile(s1 + OBH, Bhb, ldb, n0, k0, tid);
            if (PASSES == 3) cp_tile(s1 + OBL, Blb, ldb, n0, k0, tid);
            CP_COMMIT();
            CP_WAIT(1);
        } else {
            CP_WAIT(0);
        }
        __syncthreads();

        uint32_t s0 = sb + (kt & 1) * STG;
#pragma unroll
        for (int ks = 0; ks < 2; ks++) {
            uint32_t ah[2][4], al[2][4], bh[4][4], bl[4][4];
#pragma unroll
            for (int mi = 0; mi < 2; mi++) {
                uint32_t off = (uint32_t)((wm * 32 + mi * 16 + rowA) * 80 +
                                          (ks * 16 + colA) * 2);
                ldm4(ah[mi], s0 + OAH + off);
                if (PASSES >= 2) ldm4(al[mi], s0 + OAL + off);
            }
#pragma unroll
            for (int nj = 0; nj < 4; nj++) {
                uint32_t off = (uint32_t)((wn * 64 + nj * 16 + rowB) * 80 +
                                          (ks * 16 + colB) * 2);
                ldm4(bh[nj], s0 + OBH + off);
                if (PASSES == 3) ldm4(bl[nj], s0 + OBL + off);
            }
#pragma unroll
            for (int mi = 0; mi < 2; mi++)
#pragma unroll
                for (int nj = 0; nj < 4; nj++)
#pragma unroll
                    for (int sub = 0; sub < 2; sub++) {
                        float* d = acc[mi][nj * 2 + sub];
                        mma16816(d, ah[mi], &bh[nj][sub * 2]);
                        if (PASSES >= 2) mma16816(d, al[mi], &bh[nj][sub * 2]);
                        if (PASSES == 3) mma16816(d, ah[mi], &bl[nj][sub * 2]);
                    }
        }
        __syncthreads();
    }

    // epilogue
    const bool wantLo = (EPI == 1) && (bz < loBz);
#pragma unroll
    for (int mi = 0; mi < 2; mi++) {
        int rbase = m0 + wm * 32 + mi * 16 + (lane >> 2);
#pragma unroll
        for (int nj = 0; nj < 8; nj++) {
            int c0 = n0 + wn * 64 + nj * 8 + (lane & 3) * 2;
            float* d = acc[mi][nj];
#pragma unroll
            for (int hr = 0; hr < 2; hr++) {
                int r = rbase + hr * 8;
                float v0 = d[hr * 2 + 0];
                float v1 = d[hr * 2 + 1];
                if (EPI == 0) {
                    *reinterpret_cast<float2*>(&C[(size_t)bz * sC + (size_t)r * ldc + c0]) =
                        make_float2(v0, v1);
                } else if (EPI == 3) {
                    float rb = bias[(size_t)bz * sBias + r];
                    v0 += rb;
                    v1 += rb;
                    size_t o = (size_t)bz * sC + (size_t)r * ldc + c0;
                    *reinterpret_cast<__half2*>(&Oh[o]) =
                        __halves2half2(__float2half_rn(v0), __float2half_rn(v1));
                } else {
                    if (bias) {
                        v0 += bias[(size_t)bz * sBias + c0];
                        v1 += bias[(size_t)bz * sBias + c0 + 1];
                    }
                    if (EPI == 2) {
                        v0 = 0.5f * v0 * (1.0f + erff(v0 * 0.70710678118654752f));
                        v1 = 0.5f * v1 * (1.0f + erff(v1 * 0.70710678118654752f));
                    }
                    h16 h0 = __float2half_rn(v0), h1 = __float2half_rn(v1);
                    size_t o = (size_t)bz * sC + (size_t)r * ldc + c0;
                    *reinterpret_cast<__half2*>(&Oh[o]) = __halves2half2(h0, h1);
                    if (EPI == 2 || wantLo) {
                        *reinterpret_cast<__half2*>(&Ol[o]) = __halves2half2(
                            __float2half_rn(v0 - __half2float(h0)),
                            __float2half_rn(v1 - __half2float(h1)));
                    }
                }
            }
        }
    }
}

// ---------------- split-K reduce: out = p0 + p1 + bias + resid (fp32) ----------------
__global__ void reduce2_bias_resid(const float* __restrict__ p, const float* __restrict__ bias,
                                   const float* __restrict__ resid, float* __restrict__ out) {
    size_t i = (size_t)blockIdx.x * 256 + threadIdx.x;
    out[i] = p[i] + p[i + (size_t)Nn * Dd] + bias[i & (Dd - 1)] + resid[i];
}

// ---------------- weight prep: fp32 [R][C] -> fp16 [C][R] hi (+opt lo), scaled ----------------
__global__ void transpose_w(const float* __restrict__ in, h16* __restrict__ oh,
                            h16* __restrict__ ol, int R, int C, float scale) {
    __shared__ float t[32][33];
    int bz = blockIdx.z;
    size_t oz = (size_t)bz * R * C;
    int c0 = blockIdx.x * 32, r0 = blockIdx.y * 32;
    int tx = threadIdx.x, ty = threadIdx.y;  // (32,8)
#pragma unroll
    for (int k = 0; k < 4; k++) {
        int r = r0 + ty + k * 8;
        t[ty + k * 8][tx] = in[(size_t)bz * R * C + (size_t)r * C + c0 + tx] * scale;
    }
    __syncthreads();
#pragma unroll
    for (int k = 0; k < 4; k++) {
        int c = c0 + ty + k * 8;
        float v = t[tx][ty + k * 8];
        size_t i = oz + (size_t)c * R + r0 + tx;
        h16 h = __float2half_rn(v);
        oh[i] = h;
        if (ol) ol[i] = __float2half_rn(v - __half2float(h));
    }
}

// ---------------- pack QKV biases (scale folded into Q) ----------------
__global__ void pack_bias(const float* __restrict__ bq, const float* __restrict__ bk,
                          const float* __restrict__ bv, float* __restrict__ o, float s) {
    int i = blockIdx.x * 256 + threadIdx.x;  // 24*512
    int z = i >> 9, c = i & 511;
    float v = (z < 8) ? bq[z * 512 + c] * s
                      : ((z < 16) ? bk[(z - 8) * 512 + c] : bv[(z - 16) * 512 + c]);
    o[i] = v;
}

// ---------------- layernorm(512) -> fp16 hi/lo ----------------
__global__ void layernorm512_split(const float* __restrict__ x, const float* __restrict__ g,
                                   const float* __restrict__ beta,
                                   h16* __restrict__ oh, h16* __restrict__ ol) {
    int row = blockIdx.x;
    const float* xr = x + (size_t)row * Dd;
    int tid = threadIdx.x;  // 128
    float v[4];
    float s = 0.f;
#pragma unroll
    for (int i = 0; i < 4; i++) { v[i] = xr[tid + i * 128]; s += v[i]; }
    __shared__ float red[4];
#pragma unroll
    for (int o = 16; o; o >>= 1) s += __shfl_xor_sync(0xffffffffu, s, o);
    if ((tid & 31) == 0) red[tid >> 5] = s;
    __syncthreads();
    float mu = (red[0] + red[1] + red[2] + red[3]) * (1.f / 512.f);
    float vs = 0.f;
#pragma unroll
    for (int i = 0; i < 4; i++) { float t = v[i] - mu; vs += t * t; }
#pragma unroll
    for (int o = 16; o; o >>= 1) vs += __shfl_xor_sync(0xffffffffu, vs, o);
    __syncthreads();
    if ((tid & 31) == 0) red[tid >> 5] = vs;
    __syncthreads();
    float var = (red[0] + red[1] + red[2] + red[3]) * (1.f / 512.f);
    float rstd = rsqrtf(var + 1e-5f);
#pragma unroll
    for (int i = 0; i < 4; i++) {
        int c = tid + i * 128;
        float o = (v[i] - mu) * rstd * g[c] + beta[c];
        split_h(o, oh, ol, (size_t)row * Dd + c);
    }
}

// ---------------- edge dot ----------------
__global__ void edge_d_kernel(const float* __restrict__ edge_attr,
                              const float* __restrict__ edge_vec,
                              float* __restrict__ dout) {
    __shared__ float ea[4][EDd];
    int e0 = blockIdx.x * 4;
    int tid = threadIdx.x;
    for (int i = tid; i < 4 * EDd; i += 128)
        ea[i >> 6][i & 63] = edge_attr[(size_t)e0 * EDd + i];
    __syncthreads();
    int el = tid >> 5;
    int hp = tid & 31;
    const float* ev = edge_vec + hp * EDd;
    float s = 0.f;
#pragma unroll
    for (int f = 0; f < EDd; f++) s += ea[el][f] * ev[f];
    int h = hp >> 2, p = hp & 3;
    dout[((size_t)h * Ee + (e0 + el)) * Pp + p] = s;
}

// ---------------- fused bias(b) + path-bias + softmax -> fp16 hi only (vectorized) ----------------
__global__ void bias_c_softmax(const float* __restrict__ S, const float* __restrict__ b,
                               const int* __restrict__ path_idx,
                               const int* __restrict__ path_len,
                               const float* __restrict__ dmat,
                               h16* __restrict__ Sh) {
    int h = blockIdx.x;
    int row = blockIdx.y;
    const float4* r4 = reinterpret_cast<const float4*>(S + ((size_t)h * Nn + row) * Nn);
    const float4* b4 = reinterpret_cast<const float4*>(b + (size_t)row * Nn);
    const int4* pl4 = reinterpret_cast<const int4*>(path_len + (size_t)row * Nn);
    const int4* pir = reinterpret_cast<const int4*>(path_idx + (size_t)row * Nn * Pp);
    const float* dh = dmat + (size_t)h * Ee * Pp;
    int tid = threadIdx.x;  // 256
    float v[8];
    float m = -1e30f;
#pragma unroll
    for (int i = 0; i < 2; i++) {
        int idx4 = tid + i * 256;
        float4 sv = r4[idx4];
        float4 bv = b4[idx4];
        int4 pl = pl4[idx4];
        float sarr[4] = {sv.x, sv.y, sv.z, sv.w};
        float barr[4] = {bv.x, bv.y, bv.z, bv.w};
        int plarr[4] = {pl.x, pl.y, pl.z, pl.w};
#pragma unroll
        for (int j = 0; j < 4; j++) {
            int pln = plarr[j];
            float c = 0.f;
            if (pln > 0) {
                const int4 pi = pir[idx4 * 4 + j];
                float s = dh[(size_t)pi.x * 4 + 0];
                if (1 < pln) s += dh[(size_t)pi.y * 4 + 1];
                if (2 < pln) s += dh[(size_t)pi.z * 4 + 2];
                if (3 < pln) s += dh[(size_t)pi.w * 4 + 3];
                c = s / (float)pln;
            }
            float val = sarr[j] + barr[j] + c;
            v[i * 4 + j] = val;
            m = fmaxf(m, val);
        }
    }
    __shared__ float red[8];
#pragma unroll
    for (int o = 16; o; o >>= 1) m = fmaxf(m, __shfl_xor_sync(0xffffffffu, m, o));
    if ((tid & 31) == 0) red[tid >> 5] = m;
    __syncthreads();
    m = red[0];
#pragma unroll
    for (int i = 1; i < 8; i++) m = fmaxf(m, red[i]);
    float s = 0.f;
#pragma unroll
    for (int i = 0; i < 8; i++) { v[i] = __expf(v[i] - m); s += v[i]; }
#pragma unroll
    for (int o = 16; o; o >>= 1) s += __shfl_xor_sync(0xffffffffu, s, o);
    __syncthreads();
    if ((tid & 31) == 0) red[tid >> 5] = s;
    __syncthreads();
    s = red[0];
#pragma unroll
    for (int i = 1; i < 8; i++) s += red[i];
    float inv = 1.f / s;
    h2x2* out2 = reinterpret_cast<h2x2*>(Sh + ((size_t)h * Nn + row) * Nn);
#pragma unroll
    for (int i = 0; i < 2; i++) {
        int idx4 = tid + i * 256;
        h2x2 pk;
        pk.a = __halves2half2(__float2half_rn(v[i * 4 + 0] * inv),
                              __float2half_rn(v[i * 4 + 1] * inv));
        pk.b = __halves2half2(__float2half_rn(v[i * 4 + 2] * inv),
                              __float2half_rn(v[i * 4 + 3] * inv));
        out2[idx4] = pk;
    }
}

// ---------------- host ----------------
#define GETSYM(var, sym) cudaGetSymbolAddress((void**)&var, sym)

extern "C" void kernel_launch(void* const* d_in, const int* in_sizes, int n_in,
                              void* d_out, int out_size) {
    const float* x         = (const float*)d_in[0];
    const float* edge_attr = (const float*)d_in[1];
    const float* b         = (const float*)d_in[2];
    const int*   path_idx  = (const int*)d_in[3];
    const int*   path_len  = (const int*)d_in[4];
    const float* Wq        = (const float*)d_in[5];
    const float* bq        = (const float*)d_in[6];
    const float* Wk        = (const float*)d_in[7];
    const float* bk        = (const float*)d_in[8];
    const float* Wv        = (const float*)d_in[9];
    const float* bv        = (const float*)d_in[10];
    const float* edge_vec  = (const float*)d_in[11];
    const float* Wo        = (const float*)d_in[12];
    const float* bo        = (const float*)d_in[13];
    const float* ln1_g     = (const float*)d_in[14];
    const float* ln1_b     = (const float*)d_in[15];
    const float* ln2_g     = (const float*)d_in[16];
    const float* ln2_b     = (const float*)d_in[17];
    const float* W1        = (const float*)d_in[18];
    const float* b1        = (const float*)d_in[19];
    const float* W2        = (const float*)d_in[20];
    const float* b2        = (const float*)d_in[21];
    float* out = (float*)d_out;

    float *Sf, *x1f, *dmat, *bqkv;
    GETSYM(Sf, g_Sf); GETSYM(x1f, g_x1); GETSYM(dmat, g_dmat); GETSYM(bqkv, g_bqkv);
    h16 *xh, *xl, *QKVh, *QKVl, *Vth, *Sh, *mhh, *mhl, *h2h, *h2l, *ffh, *ffl;
    h16 *Wh, *Woh, *W1h, *W1l, *W2h, *W2l;
    GETSYM(xh, g_xh); GETSYM(xl, g_xl);
    GETSYM(QKVh, g_QKVh); GETSYM(QKVl, g_QKVl);
    GETSYM(Vth, g_Vth);
    GETSYM(Sh, g_Sh);
    GETSYM(mhh, g_mhh); GETSYM(mhl, g_mhl);
    GETSYM(h2h, g_h2h); GETSYM(h2l, g_h2l);
    GETSYM(ffh, g_ffh); GETSYM(ffl, g_ffl);
    GETSYM(Wh, g_Wh);
    GETSYM(Woh, g_Woh);
    GETSYM(W1h, g_W1h); GETSYM(W1l, g_W1l);
    GETSYM(W2h, g_W2h); GETSYM(W2l, g_W2l);

    const int SM1 = 40960;
    const int SM2 = 61440;
    const int SM3 = 81920;
    cudaFuncSetAttribute(gemm_h<1, 1, 2>, cudaFuncAttributeMaxDynamicSharedMemorySize, SM1);
    cudaFuncSetAttribute(gemm_h<1, 3, 2>, cudaFuncAttributeMaxDynamicSharedMemorySize, SM1);
    cudaFuncSetAttribute(gemm_h<2, 0, 2>, cudaFuncAttributeMaxDynamicSharedMemorySize, SM2);
    cudaFuncSetAttribute(gemm_h<2, 1, 2>, cudaFuncAttributeMaxDynamicSharedMemorySize, SM2);
    cudaFuncSetAttribute(gemm_h<3, 2, 1>, cudaFuncAttributeMaxDynamicSharedMemorySize, SM3);
    cudaFuncSetAttribute(gemm_h<3, 0, 1>, cudaFuncAttributeMaxDynamicSharedMemorySize, SM3);

    const float scale = 1.0f / sqrtf((float)Dd);
    dim3 tb32(32, 8);
    const long ND = (long)Nn * Dd;
    const long NN = (long)Nn * Nn;
    const long DD = (long)Dd * Dd;

    // weight prep (transpose to K-major fp16)
    transpose_w<<<dim3(16, 16, Hh), tb32>>>(Wq, Wh, nullptr, Dd, Dd, scale);
    transpose_w<<<dim3(16, 16, Hh), tb32>>>(Wk, Wh + 8 * DD, nullptr, Dd, Dd, 1.f);
    transpose_w<<<dim3(16, 16, Hh), tb32>>>(Wv, Wh + 16 * DD, nullptr, Dd, Dd, 1.f);
    transpose_w<<<dim3(16, 128, 1), tb32>>>(Wo, Woh, nullptr, Hh * Dd, Dd, 1.f);
    transpose_w<<<dim3(64, 16, 1), tb32>>>(W1, W1h, W1l, Dd, Ff, 1.f);
    transpose_w<<<dim3(16, 64, 1), tb32>>>(W2, W2h, W2l, Ff, Dd, 1.f);
    pack_bias<<<48, 256>>>(bq, bk, bv, bqkv, scale);

    // LN1, edge dots
    layernorm512_split<<<Nn, 128>>>(x, ln1_g, ln1_b, xh, xl);
    edge_d_kernel<<<Ee / 4, 128>>>(edge_attr, edge_vec, dmat);

    // Q/K: batched 2-pass GEMM (16 batches), epilogue = +bias, split fp16 (lo only for Q)
    gemm_h<2, 1, 2><<<dim3(4, 16, 16), 256, SM2>>>(
        xh, xl, Wh, nullptr, nullptr, QKVh, QKVl, bqkv,
        Dd, Dd, Dd, Dd, 0, DD, ND, Dd, 8);

    // V^T directly: Vt[h][d][n] = sum_k Wv[h][k][d]*xln[n][k] + bv[h][d]
    // (A = Wv^T K-major = Wh+16DD; B = xln; EPI=3 row-bias, hi out only)
    gemm_h<1, 3, 2><<<dim3(16, 4, Hh), 256, SM1>>>(
        Wh + 16 * DD, nullptr, xh, nullptr, nullptr, Vth, nullptr, bv,
        Dd, Dd, Dd, Nn, DD, 0, (long)Dd * Nn, Dd, 0);

    // scores: S[h] = Qs @ K^T (2-pass, fp32 out)
    gemm_h<2, 0, 2><<<dim3(16, 16, Hh), 256, SM2>>>(
        QKVh, QKVl, QKVh + 8 * ND, nullptr, Sf, nullptr, nullptr, nullptr,
        Dd, Dd, Dd, Nn, ND, ND, NN, 0, 0);

    // spatial + path bias, softmax -> fp16 hi only
    bias_c_softmax<<<dim3(Hh, Nn), 256>>>(Sf, b, path_idx, path_len, dmat, Sh);

    // attn @ V -> mh (1-pass, split fp16 hi/lo out for Wo 2-pass)
    gemm_h<1, 1, 2><<<dim3(4, 16, Hh), 256, SM1>>>(
        Sh, nullptr, Vth, nullptr, nullptr, mhh, mhl, nullptr,
        Nn, Nn, Nn, Hh * Dd, NN, (long)Dd * Nn, Dd, 0, Hh);

    // x1 = mh @ Wo + bo + x  (2-pass, split-K=2 -> partials in Sf, then reduce)
    gemm_h<2, 0, 2><<<dim3(4, 16, 2), 256, SM2>>>(
        mhh, mhl, Woh, nullptr, Sf, nullptr, nullptr, nullptr,
        Hh * Dd / 2, Hh * Dd, Hh * Dd, Dd, Hh * Dd / 2, Hh * Dd / 2, ND, 0, 0);
    reduce2_bias_resid<<<(Nn * Dd) / 256, 256>>>(Sf, bo, x, x1f);

    // LN2
    layernorm512_split<<<Nn, 128>>>(x1f, ln2_g, ln2_b, h2h, h2l);

    // ff = gelu(h2 @ W1 + b1) (3-pass, fused gelu+split)
    gemm_h<3, 2, 1><<<dim3(16, 16, 1), 256, SM3>>>(
        h2h, h2l, W1h, W1l, nullptr, ffh, ffl, b1,
        Dd, Dd, Dd, Ff, 0, 0, 0, 0, 0);

    // out = ff @ W2 + b2 + x1 (3-pass, split-K=2 -> partials in Sf, then reduce)
    gemm_h<3, 0, 1><<<dim3(4, 16, 2), 256, SM3>>>(
        ffh, ffl, W2h, W2l, Sf, nullptr, nullptr, nullptr,
        Ff / 2, Ff, Ff, Dd, Ff / 2, Ff / 2, ND, 0, 0);
    reduce2_bias_resid<<<(Nn * Dd) / 256, 256>>>(Sf, b2, x1f, out);
}

// round 14
// speedup vs baseline: 1.0989x; 1.0673x over previous
#include <cuda_runtime.h>
#include <cuda_fp16.h>
#include <math.h>
#include <stdint.h>

#define Nn 2048
#define Dd 512
#define Hh 8
#define Ff 2048
#define EDd 64
#define Pp 4
#define Ee 32768

typedef __half h16;

// ---------------- static scratch (no allocations allowed) ----------------
__device__ float g_Sf[(size_t)Hh * Nn * Nn];      // 128 MB scores (+ split-K partials reuse)
__device__ float g_x1[Nn * Dd];
__device__ float g_dmat[Hh * Ee * Pp];
__device__ float g_bqkv[24 * Dd];

__device__ h16 g_xh[Nn * Dd], g_xl[Nn * Dd];
__device__ h16 g_QKVh[16 * Nn * Dd], g_QKVl[8 * Nn * Dd];   // Q:0-7 K:8-15 (lo only for Q)
__device__ h16 g_Vth[(size_t)Hh * Dd * Nn];                  // V^T computed directly
__device__ h16 g_Sh[(size_t)Hh * Nn * Nn];                   // softmax probs, hi only
__device__ h16 g_mhh[(size_t)Nn * Hh * Dd], g_mhl[(size_t)Nn * Hh * Dd];
__device__ h16 g_h2h[Nn * Dd], g_h2l[Nn * Dd];
__device__ h16 g_ffh[Nn * Ff], g_ffl[Nn * Ff];
__device__ h16 g_Wh[24 * Dd * Dd];                            // QKV weights (transposed), hi only
__device__ h16 g_Woh[Dd * Hh * Dd];                           // Wo hi only (2-pass)
__device__ h16 g_W1h[Ff * Dd];                                // W1 hi only (2-pass)
__device__ h16 g_W2h[Dd * Ff];                                // W2 hi only (2-pass)

// ---------------- low-level helpers ----------------
__device__ __forceinline__ uint32_t smem_u32(const void* p) {
    uint32_t a;
    asm("{ .reg .u64 t; cvta.to.shared.u64 t, %1; cvt.u32.u64 %0, t; }" : "=r"(a) : "l"(p));
    return a;
}
__device__ __forceinline__ void ldm4(uint32_t* r, uint32_t addr) {
    asm volatile("ldmatrix.sync.aligned.m8n8.x4.shared.b16 {%0,%1,%2,%3}, [%4];"
                 : "=r"(r[0]), "=r"(r[1]), "=r"(r[2]), "=r"(r[3]) : "r"(addr));
}
__device__ __forceinline__ void mma16816(float* d, const uint32_t* a, const uint32_t* b) {
    asm volatile(
        "mma.sync.aligned.m16n8k16.row.col.f32.f16.f16.f32 "
        "{%0,%1,%2,%3}, {%4,%5,%6,%7}, {%8,%9}, {%0,%1,%2,%3};"
        : "+f"(d[0]), "+f"(d[1]), "+f"(d[2]), "+f"(d[3])
        : "r"(a[0]), "r"(a[1]), "r"(a[2]), "r"(a[3]), "r"(b[0]), "r"(b[1]));
}
__device__ __forceinline__ void cp16(uint32_t sdst, const void* gsrc) {
    asm volatile("cp.async.cg.shared.global [%0], [%1], 16;" :: "r"(sdst), "l"(gsrc));
}
#define CP_COMMIT() asm volatile("cp.async.commit_group;" ::: "memory")
#define CP_WAIT(n)  asm volatile("cp.async.wait_group %0;" :: "n"(n) : "memory")

// one 128x32 fp16 tile (row-major, leading dim ld) into 80B-pitched smem
__device__ __forceinline__ void cp_tile(uint32_t sdst, const h16* __restrict__ src,
                                        int ld, int row0, int k0, int tid) {
#pragma unroll
    for (int it = 0; it < 2; it++) {
        int idx = tid + it * 256;
        int r = idx >> 2, c = idx & 3;
        cp16(sdst + r * 80 + c * 16, src + (size_t)(row0 + r) * ld + k0 + c * 8);
    }
}

__device__ __forceinline__ void split_h(float v, h16* oh, h16* ol, size_t i) {
    h16 h = __float2half_rn(v);
    oh[i] = h;
    ol[i] = __float2half_rn(v - __half2float(h));
}

// ---------------- split-fp16 mma.sync GEMM: acc[M,N] = sum_k A[m,k]*B[n,k] ----------------
// CTA tile 128x128, 8 warps in 4(M)x2(N), 32x64 per warp.
// PASSES=1: Ah*Bh. PASSES=2: + Al*Bh. PASSES=3: + Ah*Bl.
// Inner loop: preload ALL fragments before the MMA block (R8 structure).
// EPI: 0 = fp32 C (also split-K partials); 1 = (acc + colbias) split fp16 (lo only if bz<loBz);
//      2 = gelu split; 3 = (acc + rowbias[m]) fp16 hi only.
template <int PASSES, int EPI, int MINB>
__global__ void __launch_bounds__(256, MINB)
gemm_h(const h16* __restrict__ Ah_, const h16* __restrict__ Al_,
       const h16* __restrict__ Bh_, const h16* __restrict__ Bl_,
       float* __restrict__ C, h16* __restrict__ Oh, h16* __restrict__ Ol,
       const float* __restrict__ bias,
       int K, int lda, int ldb, int ldc,
       long sA, long sB, long sC, long sBias, int loBz) {
    constexpr int NT = (PASSES == 1) ? 2 : ((PASSES == 2) ? 3 : 4);
    constexpr int STG = NT * 10240;
    constexpr int OAH = 0;
    constexpr int OAL = 10240;
    constexpr int OBH = (PASSES >= 2) ? 20480 : 10240;
    constexpr int OBL = 30720;
    extern __shared__ char smem[];
    const int tid = threadIdx.x;
    const int lane = tid & 31;
    const int wid = tid >> 5;
    const int wm = wid & 3;
    const int wn = wid >> 2;
    const int bz = blockIdx.z;
    const h16* Ahb = Ah_ + (size_t)bz * sA;
    const h16* Alb = (PASSES >= 2) ? Al_ + (size_t)bz * sA : nullptr;
    const h16* Bhb = Bh_ + (size_t)bz * sB;
    const h16* Blb = (PASSES == 3) ? Bl_ + (size_t)bz * sB : nullptr;
    const int m0 = blockIdx.y * 128;
    const int n0 = blockIdx.x * 128;
    const uint32_t sb = smem_u32(smem);

    float acc[2][8][4];
#pragma unroll
    for (int i = 0; i < 2; i++)
#pragma unroll
        for (int j = 0; j < 8; j++)
#pragma unroll
            for (int t = 0; t < 4; t++) acc[i][j][t] = 0.f;

    const int rowA = (lane & 15);
    const int colA = (lane >> 4) * 8;
    const int rowB = (lane & 7) + ((lane >> 4) & 1) * 8;
    const int colB = ((lane >> 3) & 1) * 8;

    const int nk = K >> 5;

    {
        cp_tile(sb + OAH, Ahb, lda, m0, 0, tid);
        if (PASSES >= 2) cp_tile(sb + OAL, Alb, lda, m0, 0, tid);
        cp_tile(sb + OBH, Bhb, ldb, n0, 0, tid);
        if (PASSES == 3) cp_tile(sb + OBL, Blb, ldb, n0, 0, tid);
        CP_COMMIT();
    }

    for (int kt = 0; kt < nk; kt++) {
        if (kt + 1 < nk) {
            uint32_t s1 = sb + ((kt + 1) & 1) * STG;
            int k0 = (kt + 1) << 5;
            cp_tile(s1 + OAH, Ahb, lda, m0, k0, tid);
            if (PASSES >= 2) cp_tile(s1 + OAL, Alb, lda, m0, k0, tid);
            cp_tile(s1 + OBH, Bhb, ldb, n0, k0, tid);
            if (PASSES == 3) cp_tile(s1 + OBL, Blb, ldb, n0, k0, tid);
            CP_COMMIT();
            CP_WAIT(1);
        } else {
            CP_WAIT(0);
        }
        __syncthreads();

        uint32_t s0 = sb + (kt & 1) * STG;
#pragma unroll
        for (int ks = 0; ks < 2; ks++) {
            uint32_t ah[2][4], al[2][4], bh[4][4], bl[4][4];
#pragma unroll
            for (int mi = 0; mi < 2; mi++) {
                uint32_t off = (uint32_t)((wm * 32 + mi * 16 + rowA) * 80 +
                                          (ks * 16 + colA) * 2);
                ldm4(ah[mi], s0 + OAH + off);
                if (PASSES >= 2) ldm4(al[mi], s0 + OAL + off);
            }
#pragma unroll
            for (int nj = 0; nj < 4; nj++) {
                uint32_t off = (uint32_t)((wn * 64 + nj * 16 + rowB) * 80 +
                                          (ks * 16 + colB) * 2);
                ldm4(bh[nj], s0 + OBH + off);
                if (PASSES == 3) ldm4(bl[nj], s0 + OBL + off);
            }
#pragma unroll
            for (int mi = 0; mi < 2; mi++)
#pragma unroll
                for (int nj = 0; nj < 4; nj++)
#pragma unroll
                    for (int sub = 0; sub < 2; sub++) {
                        float* d = acc[mi][nj * 2 + sub];
                        mma16816(d, ah[mi], &bh[nj][sub * 2]);
                        if (PASSES >= 2) mma16816(d, al[mi], &bh[nj][sub * 2]);
                        if (PASSES == 3) mma16816(d, ah[mi], &bl[nj][sub * 2]);
                    }
        }
        __syncthreads();
    }

    // epilogue
    const bool wantLo = (EPI == 1) && (bz < loBz);
#pragma unroll
    for (int mi = 0; mi < 2; mi++) {
        int rbase = m0 + wm * 32 + mi * 16 + (lane >> 2);
#pragma unroll
        for (int nj = 0; nj < 8; nj++) {
            int c0 = n0 + wn * 64 + nj * 8 + (lane & 3) * 2;
            float* d = acc[mi][nj];
#pragma unroll
            for (int hr = 0; hr < 2; hr++) {
                int r = rbase + hr * 8;
                float v0 = d[hr * 2 + 0];
                float v1 = d[hr * 2 + 1];
                if (EPI == 0) {
                    *reinterpret_cast<float2*>(&C[(size_t)bz * sC + (size_t)r * ldc + c0]) =
                        make_float2(v0, v1);
                } else if (EPI == 3) {
                    float rb = bias[(size_t)bz * sBias + r];
                    v0 += rb;
                    v1 += rb;
                    size_t o = (size_t)bz * sC + (size_t)r * ldc + c0;
                    *reinterpret_cast<__half2*>(&Oh[o]) =
                        __halves2half2(__float2half_rn(v0), __float2half_rn(v1));
                } else {
                    if (bias) {
                        v0 += bias[(size_t)bz * sBias + c0];
                        v1 += bias[(size_t)bz * sBias + c0 + 1];
                    }
                    if (EPI == 2) {
                        v0 = 0.5f * v0 * (1.0f + erff(v0 * 0.70710678118654752f));
                        v1 = 0.5f * v1 * (1.0f + erff(v1 * 0.70710678118654752f));
                    }
                    h16 h0 = __float2half_rn(v0), h1 = __float2half_rn(v1);
                    size_t o = (size_t)bz * sC + (size_t)r * ldc + c0;
                    *reinterpret_cast<__half2*>(&Oh[o]) = __halves2half2(h0, h1);
                    if (EPI == 2 || wantLo) {
                        *reinterpret_cast<__half2*>(&Ol[o]) = __halves2half2(
                            __float2half_rn(v0 - __half2float(h0)),
                            __float2half_rn(v1 - __half2float(h1)));
                    }
                }
            }
        }
    }
}

// ---------------- split-K reduce: out = p0 + p1 + bias + resid (fp32) ----------------
__global__ void reduce2_bias_resid(const float* __restrict__ p, const float* __restrict__ bias,
                                   const float* __restrict__ resid, float* __restrict__ out) {
    size_t i = (size_t)blockIdx.x * 256 + threadIdx.x;
    out[i] = p[i] + p[i + (size_t)Nn * Dd] + bias[i & (Dd - 1)] + resid[i];
}

// ---------------- weight prep: fp32 [R][C] -> fp16 [C][R] hi (+opt lo), scaled ----------------
__global__ void transpose_w(const float* __restrict__ in, h16* __restrict__ oh,
                            h16* __restrict__ ol, int R, int C, float scale) {
    __shared__ float t[32][33];
    int bz = blockIdx.z;
    size_t oz = (size_t)bz * R * C;
    int c0 = blockIdx.x * 32, r0 = blockIdx.y * 32;
    int tx = threadIdx.x, ty = threadIdx.y;  // (32,8)
#pragma unroll
    for (int k = 0; k < 4; k++) {
        int r = r0 + ty + k * 8;
        t[ty + k * 8][tx] = in[(size_t)bz * R * C + (size_t)r * C + c0 + tx] * scale;
    }
    __syncthreads();
#pragma unroll
    for (int k = 0; k < 4; k++) {
        int c = c0 + ty + k * 8;
        float v = t[tx][ty + k * 8];
        size_t i = oz + (size_t)c * R + r0 + tx;
        h16 h = __float2half_rn(v);
        oh[i] = h;
        if (ol) ol[i] = __float2half_rn(v - __half2float(h));
    }
}

// ---------------- pack QKV biases (scale folded into Q) ----------------
__global__ void pack_bias(const float* __restrict__ bq, const float* __restrict__ bk,
                          const float* __restrict__ bv, float* __restrict__ o, float s) {
    int i = blockIdx.x * 256 + threadIdx.x;  // 24*512
    int z = i >> 9, c = i & 511;
    float v = (z < 8) ? bq[z * 512 + c] * s
                      : ((z < 16) ? bk[(z - 8) * 512 + c] : bv[(z - 16) * 512 + c]);
    o[i] = v;
}

// ---------------- layernorm(512) -> fp16 hi/lo ----------------
__global__ void layernorm512_split(const float* __restrict__ x, const float* __restrict__ g,
                                   const float* __restrict__ beta,
                                   h16* __restrict__ oh, h16* __restrict__ ol) {
    int row = blockIdx.x;
    const float* xr = x + (size_t)row * Dd;
    int tid = threadIdx.x;  // 128
    float v[4];
    float s = 0.f;
#pragma unroll
    for (int i = 0; i < 4; i++) { v[i] = xr[tid + i * 128]; s += v[i]; }
    __shared__ float red[4];
#pragma unroll
    for (int o = 16; o; o >>= 1) s += __shfl_xor_sync(0xffffffffu, s, o);
    if ((tid & 31) == 0) red[tid >> 5] = s;
    __syncthreads();
    float mu = (red[0] + red[1] + red[2] + red[3]) * (1.f / 512.f);
    float vs = 0.f;
#pragma unroll
    for (int i = 0; i < 4; i++) { float t = v[i] - mu; vs += t * t; }
#pragma unroll
    for (int o = 16; o; o >>= 1) vs += __shfl_xor_sync(0xffffffffu, vs, o);
    __syncthreads();
    if ((tid & 31) == 0) red[tid >> 5] = vs;
    __syncthreads();
    float var = (red[0] + red[1] + red[2] + red[3]) * (1.f / 512.f);
    float rstd = rsqrtf(var + 1e-5f);
#pragma unroll
    for (int i = 0; i < 4; i++) {
        int c = tid + i * 128;
        float o = (v[i] - mu) * rstd * g[c] + beta[c];
        split_h(o, oh, ol, (size_t)row * Dd + c);
    }
}

// ---------------- edge dot ----------------
__global__ void edge_d_kernel(const float* __restrict__ edge_attr,
                              const float* __restrict__ edge_vec,
                              float* __restrict__ dout) {
    __shared__ float ea[4][EDd];
    int e0 = blockIdx.x * 4;
    int tid = threadIdx.x;
    for (int i = tid; i < 4 * EDd; i += 128)
        ea[i >> 6][i & 63] = edge_attr[(size_t)e0 * EDd + i];
    __syncthreads();
    int el = tid >> 5;
    int hp = tid & 31;
    const float* ev = edge_vec + hp * EDd;
    float s = 0.f;
#pragma unroll
    for (int f = 0; f < EDd; f++) s += ea[el][f] * ev[f];
    int h = hp >> 2, p = hp & 3;
    dout[((size_t)h * Ee + (e0 + el)) * Pp + p] = s;
}

// ---------------- fused bias(b) + path-bias + softmax -> fp16 hi only (scalar, R8 style) ----------------
__global__ void bias_c_softmax(const float* __restrict__ S, const float* __restrict__ b,
                               const int* __restrict__ path_idx,
                               const int* __restrict__ path_len,
                               const float* __restrict__ dmat,
                               h16* __restrict__ Sh) {
    int h = blockIdx.x;
    int row = blockIdx.y;
    const float* r = S + ((size_t)h * Nn + row) * Nn;
    const float* br = b + (size_t)row * Nn;
    const int* plr = path_len + (size_t)row * Nn;
    const int* pir = path_idx + (size_t)row * Nn * Pp;
    const float* dh = dmat + (size_t)h * Ee * Pp;
    int tid = threadIdx.x;  // 256
    float v[8];
    float m = -1e30f;
#pragma unroll
    for (int i = 0; i < 8; i++) {
        int col = tid + i * 256;
        int pl = plr[col];
        float c = 0.f;
        if (pl > 0) {
            const int4 pi = *reinterpret_cast<const int4*>(pir + (size_t)col * 4);
            float s = dh[(size_t)pi.x * 4 + 0];
            if (1 < pl) s += dh[(size_t)pi.y * 4 + 1];
            if (2 < pl) s += dh[(size_t)pi.z * 4 + 2];
            if (3 < pl) s += dh[(size_t)pi.w * 4 + 3];
            c = s / (float)pl;
        }
        v[i] = r[col] + br[col] + c;
        m = fmaxf(m, v[i]);
    }
    __shared__ float red[8];
#pragma unroll
    for (int o = 16; o; o >>= 1) m = fmaxf(m, __shfl_xor_sync(0xffffffffu, m, o));
    if ((tid & 31) == 0) red[tid >> 5] = m;
    __syncthreads();
    m = red[0];
#pragma unroll
    for (int i = 1; i < 8; i++) m = fmaxf(m, red[i]);
    float s = 0.f;
#pragma unroll
    for (int i = 0; i < 8; i++) { v[i] = __expf(v[i] - m); s += v[i]; }
#pragma unroll
    for (int o = 16; o; o >>= 1) s += __shfl_xor_sync(0xffffffffu, s, o);
    __syncthreads();
    if ((tid & 31) == 0) red[tid >> 5] = s;
    __syncthreads();
    s = red[0];
#pragma unroll
    for (int i = 1; i < 8; i++) s += red[i];
    float inv = 1.f / s;
    size_t base = ((size_t)h * Nn + row) * Nn;
#pragma unroll
    for (int i = 0; i < 8; i++)
        Sh[base + tid + i * 256] = __float2half_rn(v[i] * inv);
}

// ---------------- host ----------------
#define GETSYM(var, sym) cudaGetSymbolAddress((void**)&var, sym)

extern "C" void kernel_launch(void* const* d_in, const int* in_sizes, int n_in,
                              void* d_out, int out_size) {
    const float* x         = (const float*)d_in[0];
    const float* edge_attr = (const float*)d_in[1];
    const float* b         = (const float*)d_in[2];
    const int*   path_idx  = (const int*)d_in[3];
    const int*   path_len  = (const int*)d_in[4];
    const float* Wq        = (const float*)d_in[5];
    const float* bq        = (const float*)d_in[6];
    const float* Wk        = (const float*)d_in[7];
    const float* bk        = (const float*)d_in[8];
    const float* Wv        = (const float*)d_in[9];
    const float* bv        = (const float*)d_in[10];
    const float* edge_vec  = (const float*)d_in[11];
    const float* Wo        = (const float*)d_in[12];
    const float* bo        = (const float*)d_in[13];
    const float* ln1_g     = (const float*)d_in[14];
    const float* ln1_b     = (const float*)d_in[15];
    const float* ln2_g     = (const float*)d_in[16];
    const float* ln2_b     = (const float*)d_in[17];
    const float* W1        = (const float*)d_in[18];
    const float* b1        = (const float*)d_in[19];
    const float* W2        = (const float*)d_in[20];
    const float* b2        = (const float*)d_in[21];
    float* out = (float*)d_out;

    float *Sf, *x1f, *dmat, *bqkv;
    GETSYM(Sf, g_Sf); GETSYM(x1f, g_x1); GETSYM(dmat, g_dmat); GETSYM(bqkv, g_bqkv);
    h16 *xh, *xl, *QKVh, *QKVl, *Vth, *Sh, *mhh, *mhl, *h2h, *h2l, *ffh, *ffl;
    h16 *Wh, *Woh, *W1h, *W2h;
    GETSYM(xh, g_xh); GETSYM(xl, g_xl);
    GETSYM(QKVh, g_QKVh); GETSYM(QKVl, g_QKVl);
    GETSYM(Vth, g_Vth);
    GETSYM(Sh, g_Sh);
    GETSYM(mhh, g_mhh); GETSYM(mhl, g_mhl);
    GETSYM(h2h, g_h2h); GETSYM(h2l, g_h2l);
    GETSYM(ffh, g_ffh); GETSYM(ffl, g_ffl);
    GETSYM(Wh, g_Wh);
    GETSYM(Woh, g_Woh);
    GETSYM(W1h, g_W1h);
    GETSYM(W2h, g_W2h);

    const int SM1 = 40960;
    const int SM2 = 61440;
    cudaFuncSetAttribute(gemm_h<1, 1, 2>, cudaFuncAttributeMaxDynamicSharedMemorySize, SM1);
    cudaFuncSetAttribute(gemm_h<1, 3, 2>, cudaFuncAttributeMaxDynamicSharedMemorySize, SM1);
    cudaFuncSetAttribute(gemm_h<2, 0, 2>, cudaFuncAttributeMaxDynamicSharedMemorySize, SM2);
    cudaFuncSetAttribute(gemm_h<2, 1, 2>, cudaFuncAttributeMaxDynamicSharedMemorySize, SM2);
    cudaFuncSetAttribute(gemm_h<2, 2, 2>, cudaFuncAttributeMaxDynamicSharedMemorySize, SM2);

    const float scale = 1.0f / sqrtf((float)Dd);
    dim3 tb32(32, 8);
    const long ND = (long)Nn * Dd;
    const long NN = (long)Nn * Nn;
    const long DD = (long)Dd * Dd;

    // weight prep (transpose to K-major fp16, hi only everywhere)
    transpose_w<<<dim3(16, 16, Hh), tb32>>>(Wq, Wh, nullptr, Dd, Dd, scale);
    transpose_w<<<dim3(16, 16, Hh), tb32>>>(Wk, Wh + 8 * DD, nullptr, Dd, Dd, 1.f);
    transpose_w<<<dim3(16, 16, Hh), tb32>>>(Wv, Wh + 16 * DD, nullptr, Dd, Dd, 1.f);
    transpose_w<<<dim3(16, 128, 1), tb32>>>(Wo, Woh, nullptr, Hh * Dd, Dd, 1.f);
    transpose_w<<<dim3(64, 16, 1), tb32>>>(W1, W1h, nullptr, Dd, Ff, 1.f);
    transpose_w<<<dim3(16, 64, 1), tb32>>>(W2, W2h, nullptr, Ff, Dd, 1.f);
    pack_bias<<<48, 256>>>(bq, bk, bv, bqkv, scale);

    // LN1, edge dots
    layernorm512_split<<<Nn, 128>>>(x, ln1_g, ln1_b, xh, xl);
    edge_d_kernel<<<Ee / 4, 128>>>(edge_attr, edge_vec, dmat);

    // Q/K: batched 2-pass GEMM (16 batches), epilogue = +bias, split fp16 (lo only for Q)
    gemm_h<2, 1, 2><<<dim3(4, 16, 16), 256, SM2>>>(
        xh, xl, Wh, nullptr, nullptr, QKVh, QKVl, bqkv,
        Dd, Dd, Dd, Dd, 0, DD, ND, Dd, 8);

    // V^T directly: Vt[h][d][n] = sum_k Wv[h][k][d]*xln[n][k] + bv[h][d]
    gemm_h<1, 3, 2><<<dim3(16, 4, Hh), 256, SM1>>>(
        Wh + 16 * DD, nullptr, xh, nullptr, nullptr, Vth, nullptr, bv,
        Dd, Dd, Dd, Nn, DD, 0, (long)Dd * Nn, Dd, 0);

    // scores: S[h] = Qs @ K^T (2-pass, fp32 out)
    gemm_h<2, 0, 2><<<dim3(16, 16, Hh), 256, SM2>>>(
        QKVh, QKVl, QKVh + 8 * ND, nullptr, Sf, nullptr, nullptr, nullptr,
        Dd, Dd, Dd, Nn, ND, ND, NN, 0, 0);

    // spatial + path bias, softmax -> fp16 hi only
    bias_c_softmax<<<dim3(Hh, Nn), 256>>>(Sf, b, path_idx, path_len, dmat, Sh);

    // attn @ V -> mh (1-pass, split fp16 hi/lo out for Wo 2-pass)
    gemm_h<1, 1, 2><<<dim3(4, 16, Hh), 256, SM1>>>(
        Sh, nullptr, Vth, nullptr, nullptr, mhh, mhl, nullptr,
        Nn, Nn, Nn, Hh * Dd, NN, (long)Dd * Nn, Dd, 0, Hh);

    // x1 = mh @ Wo + bo + x  (2-pass, split-K=2 -> partials in Sf, then reduce)
    gemm_h<2, 0, 2><<<dim3(4, 16, 2), 256, SM2>>>(
        mhh, mhl, Woh, nullptr, Sf, nullptr, nullptr, nullptr,
        Hh * Dd / 2, Hh * Dd, Hh * Dd, Dd, Hh * Dd / 2, Hh * Dd / 2, ND, 0, 0);
    reduce2_bias_resid<<<(Nn * Dd) / 256, 256>>>(Sf, bo, x, x1f);

    // LN2
    layernorm512_split<<<Nn, 128>>>(x1f, ln2_g, ln2_b, h2h, h2l);

    // ff = gelu(h2 @ W1 + b1) (2-pass now: A split, W1 hi only; fused gelu+split)
    gemm_h<2, 2, 2><<<dim3(16, 16, 1), 256, SM2>>>(
        h2h, h2l, W1h, nullptr, nullptr, ffh, ffl, b1,
        Dd, Dd, Dd, Ff, 0, 0, 0, 0, 0);

    // out = ff @ W2 + b2 + x1 (2-pass now: A split, W2 hi only; split-K=2 -> reduce)
    gemm_h<2, 0, 2><<<dim3(4, 16, 2), 256, SM2>>>(
        ffh, ffl, W2h, nullptr, Sf, nullptr, nullptr, nullptr,
        Ff / 2, Ff, Ff, Dd, Ff / 2, Ff / 2, ND, 0, 0);
    reduce2_bias_resid<<<(Nn * Dd) / 256, 256>>>(Sf, b2, x1f, out);
}

// round 15
// speedup vs baseline: 1.1859x; 1.0792x over previous
#include <cuda_runtime.h>
#include <cuda_fp16.h>
#include <math.h>
#include <stdint.h>

#define Nn 2048
#define Dd 512
#define Hh 8
#define Ff 2048
#define EDd 64
#define Pp 4
#define Ee 32768

typedef __half h16;

// ---------------- static scratch (no allocations allowed) ----------------
__device__ float g_Sf[(size_t)Hh * Nn * Nn];      // 128 MB scores (+ split-K partials reuse)
__device__ float g_x1[Nn * Dd];
__device__ float g_dmat[Hh * Ee * Pp];
__device__ float g_bqkv[24 * Dd];

__device__ h16 g_xh[Nn * Dd], g_xl[Nn * Dd];
__device__ h16 g_QKVh[16 * Nn * Dd];                         // Q:0-7 K:8-15 (hi only)
__device__ h16 g_Vth[(size_t)Hh * Dd * Nn];                  // V^T computed directly
__device__ h16 g_Sh[(size_t)Hh * Nn * Nn];                   // softmax probs, hi only
__device__ h16 g_mhh[(size_t)Nn * Hh * Dd], g_mhl[(size_t)Nn * Hh * Dd];
__device__ h16 g_h2h[Nn * Dd], g_h2l[Nn * Dd];
__device__ h16 g_ffh[Nn * Ff], g_ffl[Nn * Ff];
__device__ h16 g_Wh[24 * Dd * Dd];                            // QKV weights (transposed), hi only
__device__ h16 g_Woh[Dd * Hh * Dd];                           // Wo hi only (2-pass)
__device__ h16 g_W1h[Ff * Dd];                                // W1 hi only (2-pass)
__device__ h16 g_W2h[Dd * Ff];                                // W2 hi only (2-pass)

// ---------------- low-level helpers ----------------
__device__ __forceinline__ uint32_t smem_u32(const void* p) {
    uint32_t a;
    asm("{ .reg .u64 t; cvta.to.shared.u64 t, %1; cvt.u32.u64 %0, t; }" : "=r"(a) : "l"(p));
    return a;
}
__device__ __forceinline__ void ldm4(uint32_t* r, uint32_t addr) {
    asm volatile("ldmatrix.sync.aligned.m8n8.x4.shared.b16 {%0,%1,%2,%3}, [%4];"
                 : "=r"(r[0]), "=r"(r[1]), "=r"(r[2]), "=r"(r[3]) : "r"(addr));
}
__device__ __forceinline__ void mma16816(float* d, const uint32_t* a, const uint32_t* b) {
    asm volatile(
        "mma.sync.aligned.m16n8k16.row.col.f32.f16.f16.f32 "
        "{%0,%1,%2,%3}, {%4,%5,%6,%7}, {%8,%9}, {%0,%1,%2,%3};"
        : "+f"(d[0]), "+f"(d[1]), "+f"(d[2]), "+f"(d[3])
        : "r"(a[0]), "r"(a[1]), "r"(a[2]), "r"(a[3]), "r"(b[0]), "r"(b[1]));
}
__device__ __forceinline__ void cp16(uint32_t sdst, const void* gsrc) {
    asm volatile("cp.async.cg.shared.global [%0], [%1], 16;" :: "r"(sdst), "l"(gsrc));
}
#define CP_COMMIT() asm volatile("cp.async.commit_group;" ::: "memory")
#define CP_WAIT(n)  asm volatile("cp.async.wait_group %0;" :: "n"(n) : "memory")

// one 128x32 fp16 tile (row-major, leading dim ld) into 80B-pitched smem
__device__ __forceinline__ void cp_tile(uint32_t sdst, const h16* __restrict__ src,
                                        int ld, int row0, int k0, int tid) {
#pragma unroll
    for (int it = 0; it < 2; it++) {
        int idx = tid + it * 256;
        int r = idx >> 2, c = idx & 3;
        cp16(sdst + r * 80 + c * 16, src + (size_t)(row0 + r) * ld + k0 + c * 8);
    }
}

__device__ __forceinline__ void split_h(float v, h16* oh, h16* ol, size_t i) {
    h16 h = __float2half_rn(v);
    oh[i] = h;
    ol[i] = __float2half_rn(v - __half2float(h));
}

// ---------------- split-fp16 mma.sync GEMM: acc[M,N] = sum_k A[m,k]*B[n,k] ----------------
// CTA tile 128x128, 8 warps in 4(M)x2(N), 32x64 per warp.
// PASSES=1: Ah*Bh. PASSES=2: + Al*Bh. PASSES=3: + Ah*Bl.
// Inner loop: preload ALL fragments before the MMA block (R8 structure).
// EPI: 0 = fp32 C (also split-K partials); 1 = (acc + colbias) split fp16 (lo only if bz<loBz);
//      2 = gelu split; 3 = (acc + rowbias[m]) fp16 hi only.
template <int PASSES, int EPI, int MINB>
__global__ void __launch_bounds__(256, MINB)
gemm_h(const h16* __restrict__ Ah_, const h16* __restrict__ Al_,
       const h16* __restrict__ Bh_, const h16* __restrict__ Bl_,
       float* __restrict__ C, h16* __restrict__ Oh, h16* __restrict__ Ol,
       const float* __restrict__ bias,
       int K, int lda, int ldb, int ldc,
       long sA, long sB, long sC, long sBias, int loBz) {
    constexpr int NT = (PASSES == 1) ? 2 : ((PASSES == 2) ? 3 : 4);
    constexpr int STG = NT * 10240;
    constexpr int OAH = 0;
    constexpr int OAL = 10240;
    constexpr int OBH = (PASSES >= 2) ? 20480 : 10240;
    constexpr int OBL = 30720;
    extern __shared__ char smem[];
    const int tid = threadIdx.x;
    const int lane = tid & 31;
    const int wid = tid >> 5;
    const int wm = wid & 3;
    const int wn = wid >> 2;
    const int bz = blockIdx.z;
    const h16* Ahb = Ah_ + (size_t)bz * sA;
    const h16* Alb = (PASSES >= 2) ? Al_ + (size_t)bz * sA : nullptr;
    const h16* Bhb = Bh_ + (size_t)bz * sB;
    const h16* Blb = (PASSES == 3) ? Bl_ + (size_t)bz * sB : nullptr;
    const int m0 = blockIdx.y * 128;
    const int n0 = blockIdx.x * 128;
    const uint32_t sb = smem_u32(smem);

    float acc[2][8][4];
#pragma unroll
    for (int i = 0; i < 2; i++)
#pragma unroll
        for (int j = 0; j < 8; j++)
#pragma unroll
            for (int t = 0; t < 4; t++) acc[i][j][t] = 0.f;

    const int rowA = (lane & 15);
    const int colA = (lane >> 4) * 8;
    const int rowB = (lane & 7) + ((lane >> 4) & 1) * 8;
    const int colB = ((lane >> 3) & 1) * 8;

    const int nk = K >> 5;

    {
        cp_tile(sb + OAH, Ahb, lda, m0, 0, tid);
        if (PASSES >= 2) cp_tile(sb + OAL, Alb, lda, m0, 0, tid);
        cp_tile(sb + OBH, Bhb, ldb, n0, 0, tid);
        if (PASSES == 3) cp_tile(sb + OBL, Blb, ldb, n0, 0, tid);
        CP_COMMIT();
    }

    for (int kt = 0; kt < nk; kt++) {
        if (kt + 1 < nk) {
            uint32_t s1 = sb + ((kt + 1) & 1) * STG;
            int k0 = (kt + 1) << 5;
            cp_tile(s1 + OAH, Ahb, lda, m0, k0, tid);
            if (PASSES >= 2) cp_tile(s1 + OAL, Alb, lda, m0, k0, tid);
            cp_tile(s1 + OBH, Bhb, ldb, n0, k0, tid);
            if (PASSES == 3) cp_tile(s1 + OBL, Blb, ldb, n0, k0, tid);
            CP_COMMIT();
            CP_WAIT(1);
        } else {
            CP_WAIT(0);
        }
        __syncthreads();

        uint32_t s0 = sb + (kt & 1) * STG;
#pragma unroll
        for (int ks = 0; ks < 2; ks++) {
            uint32_t ah[2][4], al[2][4], bh[4][4], bl[4][4];
#pragma unroll
            for (int mi = 0; mi < 2; mi++) {
                uint32_t off = (uint32_t)((wm * 32 + mi * 16 + rowA) * 80 +
                                          (ks * 16 + colA) * 2);
                ldm4(ah[mi], s0 + OAH + off);
                if (PASSES >= 2) ldm4(al[mi], s0 + OAL + off);
            }
#pragma unroll
            for (int nj = 0; nj < 4; nj++) {
                uint32_t off = (uint32_t)((wn * 64 + nj * 16 + rowB) * 80 +
                                          (ks * 16 + colB) * 2);
                ldm4(bh[nj], s0 + OBH + off);
                if (PASSES == 3) ldm4(bl[nj], s0 + OBL + off);
            }
#pragma unroll
            for (int mi = 0; mi < 2; mi++)
#pragma unroll
                for (int nj = 0; nj < 4; nj++)
#pragma unroll
                    for (int sub = 0; sub < 2; sub++) {
                        float* d = acc[mi][nj * 2 + sub];
                        mma16816(d, ah[mi], &bh[nj][sub * 2]);
                        if (PASSES >= 2) mma16816(d, al[mi], &bh[nj][sub * 2]);
                        if (PASSES == 3) mma16816(d, ah[mi], &bl[nj][sub * 2]);
                    }
        }
        __syncthreads();
    }

    // epilogue
    const bool wantLo = (EPI == 1) && (bz < loBz);
#pragma unroll
    for (int mi = 0; mi < 2; mi++) {
        int rbase = m0 + wm * 32 + mi * 16 + (lane >> 2);
#pragma unroll
        for (int nj = 0; nj < 8; nj++) {
            int c0 = n0 + wn * 64 + nj * 8 + (lane & 3) * 2;
            float* d = acc[mi][nj];
#pragma unroll
            for (int hr = 0; hr < 2; hr++) {
                int r = rbase + hr * 8;
                float v0 = d[hr * 2 + 0];
                float v1 = d[hr * 2 + 1];
                if (EPI == 0) {
                    *reinterpret_cast<float2*>(&C[(size_t)bz * sC + (size_t)r * ldc + c0]) =
                        make_float2(v0, v1);
                } else if (EPI == 3) {
                    float rb = bias[(size_t)bz * sBias + r];
                    v0 += rb;
                    v1 += rb;
                    size_t o = (size_t)bz * sC + (size_t)r * ldc + c0;
                    *reinterpret_cast<__half2*>(&Oh[o]) =
                        __halves2half2(__float2half_rn(v0), __float2half_rn(v1));
                } else {
                    if (bias) {
                        v0 += bias[(size_t)bz * sBias + c0];
                        v1 += bias[(size_t)bz * sBias + c0 + 1];
                    }
                    if (EPI == 2) {
                        v0 = 0.5f * v0 * (1.0f + erff(v0 * 0.70710678118654752f));
                        v1 = 0.5f * v1 * (1.0f + erff(v1 * 0.70710678118654752f));
                    }
                    h16 h0 = __float2half_rn(v0), h1 = __float2half_rn(v1);
                    size_t o = (size_t)bz * sC + (size_t)r * ldc + c0;
                    *reinterpret_cast<__half2*>(&Oh[o]) = __halves2half2(h0, h1);
                    if (EPI == 2 || wantLo) {
                        *reinterpret_cast<__half2*>(&Ol[o]) = __halves2half2(
                            __float2half_rn(v0 - __half2float(h0)),
                            __float2half_rn(v1 - __half2float(h1)));
                    }
                }
            }
        }
    }
}

// ---------------- split-K reduce: out = p0 + p1 + bias + resid (fp32) ----------------
__global__ void reduce2_bias_resid(const float* __restrict__ p, const float* __restrict__ bias,
                                   const float* __restrict__ resid, float* __restrict__ out) {
    size_t i = (size_t)blockIdx.x * 256 + threadIdx.x;
    out[i] = p[i] + p[i + (size_t)Nn * Dd] + bias[i & (Dd - 1)] + resid[i];
}

// ---------------- fused: x1 = p0+p1+bo+x ; h2 = LN(x1) -> fp16 hi/lo ----------------
__global__ void reduce2_ln_split(const float* __restrict__ p, const float* __restrict__ bias,
                                 const float* __restrict__ resid, const float* __restrict__ g,
                                 const float* __restrict__ beta, float* __restrict__ x1,
                                 h16* __restrict__ oh, h16* __restrict__ ol) {
    int row = blockIdx.x;
    int tid = threadIdx.x;  // 128
    size_t base = (size_t)row * Dd;
    float v[4];
    float s = 0.f;
#pragma unroll
    for (int i = 0; i < 4; i++) {
        int c = tid + i * 128;
        float t = p[base + c] + p[base + c + (size_t)Nn * Dd] + bias[c] + resid[base + c];
        v[i] = t;
        x1[base + c] = t;
        s += t;
    }
    __shared__ float red[4];
#pragma unroll
    for (int o = 16; o; o >>= 1) s += __shfl_xor_sync(0xffffffffu, s, o);
    if ((tid & 31) == 0) red[tid >> 5] = s;
    __syncthreads();
    float mu = (red[0] + red[1] + red[2] + red[3]) * (1.f / 512.f);
    float vs = 0.f;
#pragma unroll
    for (int i = 0; i < 4; i++) { float t = v[i] - mu; vs += t * t; }
#pragma unroll
    for (int o = 16; o; o >>= 1) vs += __shfl_xor_sync(0xffffffffu, vs, o);
    __syncthreads();
    if ((tid & 31) == 0) red[tid >> 5] = vs;
    __syncthreads();
    float var = (red[0] + red[1] + red[2] + red[3]) * (1.f / 512.f);
    float rstd = rsqrtf(var + 1e-5f);
#pragma unroll
    for (int i = 0; i < 4; i++) {
        int c = tid + i * 128;
        float o = (v[i] - mu) * rstd * g[c] + beta[c];
        split_h(o, oh, ol, base + c);
    }
}

// ---------------- weight prep: fp32 [R][C] -> fp16 [C][R] hi (+opt lo), scaled ----------------
__global__ void transpose_w(const float* __restrict__ in, h16* __restrict__ oh,
                            h16* __restrict__ ol, int R, int C, float scale) {
    __shared__ float t[32][33];
    int bz = blockIdx.z;
    size_t oz = (size_t)bz * R * C;
    int c0 = blockIdx.x * 32, r0 = blockIdx.y * 32;
    int tx = threadIdx.x, ty = threadIdx.y;  // (32,8)
#pragma unroll
    for (int k = 0; k < 4; k++) {
        int r = r0 + ty + k * 8;
        t[ty + k * 8][tx] = in[(size_t)bz * R * C + (size_t)r * C + c0 + tx] * scale;
    }
    __syncthreads();
#pragma unroll
    for (int k = 0; k < 4; k++) {
        int c = c0 + ty + k * 8;
        float v = t[tx][ty + k * 8];
        size_t i = oz + (size_t)c * R + r0 + tx;
        h16 h = __float2half_rn(v);
        oh[i] = h;
        if (ol) ol[i] = __float2half_rn(v - __half2float(h));
    }
}

// ---------------- pack QKV biases (scale folded into Q) ----------------
__global__ void pack_bias(const float* __restrict__ bq, const float* __restrict__ bk,
                          const float* __restrict__ bv, float* __restrict__ o, float s) {
    int i = blockIdx.x * 256 + threadIdx.x;  // 24*512
    int z = i >> 9, c = i & 511;
    float v = (z < 8) ? bq[z * 512 + c] * s
                      : ((z < 16) ? bk[(z - 8) * 512 + c] : bv[(z - 16) * 512 + c]);
    o[i] = v;
}

// ---------------- layernorm(512) -> fp16 hi/lo ----------------
__global__ void layernorm512_split(const float* __restrict__ x, const float* __restrict__ g,
                                   const float* __restrict__ beta,
                                   h16* __restrict__ oh, h16* __restrict__ ol) {
    int row = blockIdx.x;
    const float* xr = x + (size_t)row * Dd;
    int tid = threadIdx.x;  // 128
    float v[4];
    float s = 0.f;
#pragma unroll
    for (int i = 0; i < 4; i++) { v[i] = xr[tid + i * 128]; s += v[i]; }
    __shared__ float red[4];
#pragma unroll
    for (int o = 16; o; o >>= 1) s += __shfl_xor_sync(0xffffffffu, s, o);
    if ((tid & 31) == 0) red[tid >> 5] = s;
    __syncthreads();
    float mu = (red[0] + red[1] + red[2] + red[3]) * (1.f / 512.f);
    float vs = 0.f;
#pragma unroll
    for (int i = 0; i < 4; i++) { float t = v[i] - mu; vs += t * t; }
#pragma unroll
    for (int o = 16; o; o >>= 1) vs += __shfl_xor_sync(0xffffffffu, vs, o);
    __syncthreads();
    if ((tid & 31) == 0) red[tid >> 5] = vs;
    __syncthreads();
    float var = (red[0] + red[1] + red[2] + red[3]) * (1.f / 512.f);
    float rstd = rsqrtf(var + 1e-5f);
#pragma unroll
    for (int i = 0; i < 4; i++) {
        int c = tid + i * 128;
        float o = (v[i] - mu) * rstd * g[c] + beta[c];
        split_h(o, oh, ol, (size_t)row * Dd + c);
    }
}

// ---------------- edge dot ----------------
__global__ void edge_d_kernel(const float* __restrict__ edge_attr,
                              const float* __restrict__ edge_vec,
                              float* __restrict__ dout) {
    __shared__ float ea[4][EDd];
    int e0 = blockIdx.x * 4;
    int tid = threadIdx.x;
    for (int i = tid; i < 4 * EDd; i += 128)
        ea[i >> 6][i & 63] = edge_attr[(size_t)e0 * EDd + i];
    __syncthreads();
    int el = tid >> 5;
    int hp = tid & 31;
    const float* ev = edge_vec + hp * EDd;
    float s = 0.f;
#pragma unroll
    for (int f = 0; f < EDd; f++) s += ea[el][f] * ev[f];
    int h = hp >> 2, p = hp & 3;
    dout[((size_t)h * Ee + (e0 + el)) * Pp + p] = s;
}

// ---------------- fused bias(b) + path-bias + softmax -> fp16 hi only ----------------
__global__ void bias_c_softmax(const float* __restrict__ S, const float* __restrict__ b,
                               const int* __restrict__ path_idx,
                               const int* __restrict__ path_len,
                               const float* __restrict__ dmat,
                               h16* __restrict__ Sh) {
    int h = blockIdx.x;
    int row = blockIdx.y;
    const float* r = S + ((size_t)h * Nn + row) * Nn;
    const float* br = b + (size_t)row * Nn;
    const int* plr = path_len + (size_t)row * Nn;
    const int* pir = path_idx + (size_t)row * Nn * Pp;
    const float* dh = dmat + (size_t)h * Ee * Pp;
    int tid = threadIdx.x;  // 256
    float v[8];
    float m = -1e30f;
#pragma unroll
    for (int i = 0; i < 8; i++) {
        int col = tid + i * 256;
        int pl = plr[col];
        float c = 0.f;
        if (pl > 0) {
            const int4 pi = *reinterpret_cast<const int4*>(pir + (size_t)col * 4);
            float s = dh[(size_t)pi.x * 4 + 0];
            if (1 < pl) s += dh[(size_t)pi.y * 4 + 1];
            if (2 < pl) s += dh[(size_t)pi.z * 4 + 2];
            if (3 < pl) s += dh[(size_t)pi.w * 4 + 3];
            c = s / (float)pl;
        }
        v[i] = r[col] + br[col] + c;
        m = fmaxf(m, v[i]);
    }
    __shared__ float red[8];
#pragma unroll
    for (int o = 16; o; o >>= 1) m = fmaxf(m, __shfl_xor_sync(0xffffffffu, m, o));
    if ((tid & 31) == 0) red[tid >> 5] = m;
    __syncthreads();
    m = red[0];
#pragma unroll
    for (int i = 1; i < 8; i++) m = fmaxf(m, red[i]);
    float s = 0.f;
#pragma unroll
    for (int i = 0; i < 8; i++) { v[i] = __expf(v[i] - m); s += v[i]; }
#pragma unroll
    for (int o = 16; o; o >>= 1) s += __shfl_xor_sync(0xffffffffu, s, o);
    __syncthreads();
    if ((tid & 31) == 0) red[tid >> 5] = s;
    __syncthreads();
    s = red[0];
#pragma unroll
    for (int i = 1; i < 8; i++) s += red[i];
    float inv = 1.f / s;
    size_t base = ((size_t)h * Nn + row) * Nn;
#pragma unroll
    for (int i = 0; i < 8; i++)
        Sh[base + tid + i * 256] = __float2half_rn(v[i] * inv);
}

// ---------------- host ----------------
#define GETSYM(var, sym) cudaGetSymbolAddress((void**)&var, sym)

extern "C" void kernel_launch(void* const* d_in, const int* in_sizes, int n_in,
                              void* d_out, int out_size) {
    const float* x         = (const float*)d_in[0];
    const float* edge_attr = (const float*)d_in[1];
    const float* b         = (const float*)d_in[2];
    const int*   path_idx  = (const int*)d_in[3];
    const int*   path_len  = (const int*)d_in[4];
    const float* Wq        = (const float*)d_in[5];
    const float* bq        = (const float*)d_in[6];
    const float* Wk        = (const float*)d_in[7];
    const float* bk        = (const float*)d_in[8];
    const float* Wv        = (const float*)d_in[9];
    const float* bv        = (const float*)d_in[10];
    const float* edge_vec  = (const float*)d_in[11];
    const float* Wo        = (const float*)d_in[12];
    const float* bo        = (const float*)d_in[13];
    const float* ln1_g     = (const float*)d_in[14];
    const float* ln1_b     = (const float*)d_in[15];
    const float* ln2_g     = (const float*)d_in[16];
    const float* ln2_b     = (const float*)d_in[17];
    const float* W1        = (const float*)d_in[18];
    const float* b1        = (const float*)d_in[19];
    const float* W2        = (const float*)d_in[20];
    const float* b2        = (const float*)d_in[21];
    float* out = (float*)d_out;

    float *Sf, *x1f, *dmat, *bqkv;
    GETSYM(Sf, g_Sf); GETSYM(x1f, g_x1); GETSYM(dmat, g_dmat); GETSYM(bqkv, g_bqkv);
    h16 *xh, *xl, *QKVh, *Vth, *Sh, *mhh, *mhl, *h2h, *h2l, *ffh, *ffl;
    h16 *Wh, *Woh, *W1h, *W2h;
    GETSYM(xh, g_xh); GETSYM(xl, g_xl);
    GETSYM(QKVh, g_QKVh);
    GETSYM(Vth, g_Vth);
    GETSYM(Sh, g_Sh);
    GETSYM(mhh, g_mhh); GETSYM(mhl, g_mhl);
    GETSYM(h2h, g_h2h); GETSYM(h2l, g_h2l);
    GETSYM(ffh, g_ffh); GETSYM(ffl, g_ffl);
    GETSYM(Wh, g_Wh);
    GETSYM(Woh, g_Woh);
    GETSYM(W1h, g_W1h);
    GETSYM(W2h, g_W2h);

    const int SM1 = 40960;
    const int SM2 = 61440;
    cudaFuncSetAttribute(gemm_h<1, 0, 2>, cudaFuncAttributeMaxDynamicSharedMemorySize, SM1);
    cudaFuncSetAttribute(gemm_h<1, 1, 2>, cudaFuncAttributeMaxDynamicSharedMemorySize, SM1);
    cudaFuncSetAttribute(gemm_h<1, 3, 2>, cudaFuncAttributeMaxDynamicSharedMemorySize, SM1);
    cudaFuncSetAttribute(gemm_h<2, 0, 2>, cudaFuncAttributeMaxDynamicSharedMemorySize, SM2);
    cudaFuncSetAttribute(gemm_h<2, 1, 2>, cudaFuncAttributeMaxDynamicSharedMemorySize, SM2);
    cudaFuncSetAttribute(gemm_h<2, 2, 2>, cudaFuncAttributeMaxDynamicSharedMemorySize, SM2);

    const float scale = 1.0f / sqrtf((float)Dd);
    dim3 tb32(32, 8);
    const long ND = (long)Nn * Dd;
    const long NN = (long)Nn * Nn;
    const long DD = (long)Dd * Dd;

    // weight prep (transpose to K-major fp16, hi only everywhere)
    transpose_w<<<dim3(16, 16, Hh), tb32>>>(Wq, Wh, nullptr, Dd, Dd, scale);
    transpose_w<<<dim3(16, 16, Hh), tb32>>>(Wk, Wh + 8 * DD, nullptr, Dd, Dd, 1.f);
    transpose_w<<<dim3(16, 16, Hh), tb32>>>(Wv, Wh + 16 * DD, nullptr, Dd, Dd, 1.f);
    transpose_w<<<dim3(16, 128, 1), tb32>>>(Wo, Woh, nullptr, Hh * Dd, Dd, 1.f);
    transpose_w<<<dim3(64, 16, 1), tb32>>>(W1, W1h, nullptr, Dd, Ff, 1.f);
    transpose_w<<<dim3(16, 64, 1), tb32>>>(W2, W2h, nullptr, Ff, Dd, 1.f);
    pack_bias<<<48, 256>>>(bq, bk, bv, bqkv, scale);

    // LN1, edge dots
    layernorm512_split<<<Nn, 128>>>(x, ln1_g, ln1_b, xh, xl);
    edge_d_kernel<<<Ee / 4, 128>>>(edge_attr, edge_vec, dmat);

    // Q/K: batched 2-pass GEMM (16 batches), epilogue = +bias, hi out only (loBz=0)
    gemm_h<2, 1, 2><<<dim3(4, 16, 16), 256, SM2>>>(
        xh, xl, Wh, nullptr, nullptr, QKVh, nullptr, bqkv,
        Dd, Dd, Dd, Dd, 0, DD, ND, Dd, 0);

    // V^T directly: Vt[h][d][n] = sum_k Wv[h][k][d]*xln[n][k] + bv[h][d]
    gemm_h<1, 3, 2><<<dim3(16, 4, Hh), 256, SM1>>>(
        Wh + 16 * DD, nullptr, xh, nullptr, nullptr, Vth, nullptr, bv,
        Dd, Dd, Dd, Nn, DD, 0, (long)Dd * Nn, Dd, 0);

    // scores: S[h] = Qs @ K^T (1-pass now, fp32 out)
    gemm_h<1, 0, 2><<<dim3(16, 16, Hh), 256, SM1>>>(
        QKVh, nullptr, QKVh + 8 * ND, nullptr, Sf, nullptr, nullptr, nullptr,
        Dd, Dd, Dd, Nn, ND, ND, NN, 0, 0);

    // spatial + path bias, softmax -> fp16 hi only
    bias_c_softmax<<<dim3(Hh, Nn), 256>>>(Sf, b, path_idx, path_len, dmat, Sh);

    // attn @ V -> mh (1-pass, split fp16 hi/lo out for Wo 2-pass)
    gemm_h<1, 1, 2><<<dim3(4, 16, Hh), 256, SM1>>>(
        Sh, nullptr, Vth, nullptr, nullptr, mhh, mhl, nullptr,
        Nn, Nn, Nn, Hh * Dd, NN, (long)Dd * Nn, Dd, 0, Hh);

    // x1 = mh @ Wo + bo + x  (2-pass, split-K=2 -> partials in Sf, fused reduce+LN2)
    gemm_h<2, 0, 2><<<dim3(4, 16, 2), 256, SM2>>>(
        mhh, mhl, Woh, nullptr, Sf, nullptr, nullptr, nullptr,
        Hh * Dd / 2, Hh * Dd, Hh * Dd, Dd, Hh * Dd / 2, Hh * Dd / 2, ND, 0, 0);
    reduce2_ln_split<<<Nn, 128>>>(Sf, bo, x, ln2_g, ln2_b, x1f, h2h, h2l);

    // ff = gelu(h2 @ W1 + b1) (2-pass: A split, W1 hi only; fused gelu+split)
    gemm_h<2, 2, 2><<<dim3(16, 16, 1), 256, SM2>>>(
        h2h, h2l, W1h, nullptr, nullptr, ffh, ffl, b1,
        Dd, Dd, Dd, Ff, 0, 0, 0, 0, 0);

    // out = ff @ W2 + b2 + x1 (2-pass: A split, W2 hi only; split-K=2 -> reduce)
    gemm_h<2, 0, 2><<<dim3(4, 16, 2), 256, SM2>>>(
        ffh, ffl, W2h, nullptr, Sf, nullptr, nullptr, nullptr,
        Ff / 2, Ff, Ff, Dd, Ff / 2, Ff / 2, ND, 0, 0);
    reduce2_bias_resid<<<(Nn * Dd) / 256, 256>>>(Sf, b2, x1f, out);
}

// round 16
// speedup vs baseline: 1.2541x; 1.0575x over previous
#include <cuda_runtime.h>
#include <cuda_fp16.h>
#include <math.h>
#include <stdint.h>

#define Nn 2048
#define Dd 512
#define Hh 8
#define Ff 2048
#define EDd 64
#define Pp 4
#define Ee 32768

typedef __half h16;

// ---------------- static scratch (no allocations allowed) ----------------
__device__ float g_Sf[(size_t)Hh * Nn * Nn];      // 128 MB scores (+ split-K partials reuse)
__device__ float g_x1[Nn * Dd];
__device__ float g_dmat[Hh * Ee * Pp];
__device__ float g_bqkv[24 * Dd];

__device__ h16 g_xh[Nn * Dd];
__device__ h16 g_QKVh[16 * Nn * Dd];                         // Q:0-7 K:8-15 (hi only)
__device__ h16 g_Vth[(size_t)Hh * Dd * Nn];                  // V^T computed directly
__device__ h16 g_Sh[(size_t)Hh * Nn * Nn];                   // softmax probs, hi only
__device__ h16 g_mhh[(size_t)Nn * Hh * Dd];
__device__ h16 g_h2h[Nn * Dd], g_h2l[Nn * Dd];
__device__ h16 g_ffh[Nn * Ff], g_ffl[Nn * Ff];
__device__ h16 g_Wh[24 * Dd * Dd];                            // QKV weights (transposed), hi only
__device__ h16 g_Woh[Dd * Hh * Dd];                           // Wo hi only (1-pass)
__device__ h16 g_W1h[Ff * Dd];                                // W1 hi only (2-pass)
__device__ h16 g_W2h[Dd * Ff];                                // W2 hi only (2-pass)

// ---------------- low-level helpers ----------------
__device__ __forceinline__ uint32_t smem_u32(const void* p) {
    uint32_t a;
    asm("{ .reg .u64 t; cvta.to.shared.u64 t, %1; cvt.u32.u64 %0, t; }" : "=r"(a) : "l"(p));
    return a;
}
__device__ __forceinline__ void ldm4(uint32_t* r, uint32_t addr) {
    asm volatile("ldmatrix.sync.aligned.m8n8.x4.shared.b16 {%0,%1,%2,%3}, [%4];"
                 : "=r"(r[0]), "=r"(r[1]), "=r"(r[2]), "=r"(r[3]) : "r"(addr));
}
__device__ __forceinline__ void mma16816(float* d, const uint32_t* a, const uint32_t* b) {
    asm volatile(
        "mma.sync.aligned.m16n8k16.row.col.f32.f16.f16.f32 "
        "{%0,%1,%2,%3}, {%4,%5,%6,%7}, {%8,%9}, {%0,%1,%2,%3};"
        : "+f"(d[0]), "+f"(d[1]), "+f"(d[2]), "+f"(d[3])
        : "r"(a[0]), "r"(a[1]), "r"(a[2]), "r"(a[3]), "r"(b[0]), "r"(b[1]));
}
__device__ __forceinline__ void cp16(uint32_t sdst, const void* gsrc) {
    asm volatile("cp.async.cg.shared.global [%0], [%1], 16;" :: "r"(sdst), "l"(gsrc));
}
#define CP_COMMIT() asm volatile("cp.async.commit_group;" ::: "memory")
#define CP_WAIT(n)  asm volatile("cp.async.wait_group %0;" :: "n"(n) : "memory")

// one 128x32 fp16 tile (row-major, leading dim ld) into 80B-pitched smem
__device__ __forceinline__ void cp_tile(uint32_t sdst, const h16* __restrict__ src,
                                        int ld, int row0, int k0, int tid) {
#pragma unroll
    for (int it = 0; it < 2; it++) {
        int idx = tid + it * 256;
        int r = idx >> 2, c = idx & 3;
        cp16(sdst + r * 80 + c * 16, src + (size_t)(row0 + r) * ld + k0 + c * 8);
    }
}

__device__ __forceinline__ void split_h(float v, h16* oh, h16* ol, size_t i) {
    h16 h = __float2half_rn(v);
    oh[i] = h;
    if (ol) ol[i] = __float2half_rn(v - __half2float(h));
}

// ---------------- split-fp16 mma.sync GEMM: acc[M,N] = sum_k A[m,k]*B[n,k] ----------------
// CTA tile 128x128, 8 warps in 4(M)x2(N), 32x64 per warp.
// PASSES=1: Ah*Bh. PASSES=2: + Al*Bh. PASSES=3: + Ah*Bl.
// Inner loop: preload ALL fragments before the MMA block (R8 structure).
// EPI: 0 = fp32 C (also split-K partials); 1 = (acc + colbias) split fp16 (lo only if bz<loBz);
//      2 = gelu split; 3 = (acc + rowbias[m]) fp16 hi only.
template <int PASSES, int EPI, int MINB>
__global__ void __launch_bounds__(256, MINB)
gemm_h(const h16* __restrict__ Ah_, const h16* __restrict__ Al_,
       const h16* __restrict__ Bh_, const h16* __restrict__ Bl_,
       float* __restrict__ C, h16* __restrict__ Oh, h16* __restrict__ Ol,
       const float* __restrict__ bias,
       int K, int lda, int ldb, int ldc,
       long sA, long sB, long sC, long sBias, int loBz) {
    constexpr int NT = (PASSES == 1) ? 2 : ((PASSES == 2) ? 3 : 4);
    constexpr int STG = NT * 10240;
    constexpr int OAH = 0;
    constexpr int OAL = 10240;
    constexpr int OBH = (PASSES >= 2) ? 20480 : 10240;
    constexpr int OBL = 30720;
    extern __shared__ char smem[];
    const int tid = threadIdx.x;
    const int lane = tid & 31;
    const int wid = tid >> 5;
    const int wm = wid & 3;
    const int wn = wid >> 2;
    const int bz = blockIdx.z;
    const h16* Ahb = Ah_ + (size_t)bz * sA;
    const h16* Alb = (PASSES >= 2) ? Al_ + (size_t)bz * sA : nullptr;
    const h16* Bhb = Bh_ + (size_t)bz * sB;
    const h16* Blb = (PASSES == 3) ? Bl_ + (size_t)bz * sB : nullptr;
    const int m0 = blockIdx.y * 128;
    const int n0 = blockIdx.x * 128;
    const uint32_t sb = smem_u32(smem);

    float acc[2][8][4];
#pragma unroll
    for (int i = 0; i < 2; i++)
#pragma unroll
        for (int j = 0; j < 8; j++)
#pragma unroll
            for (int t = 0; t < 4; t++) acc[i][j][t] = 0.f;

    const int rowA = (lane & 15);
    const int colA = (lane >> 4) * 8;
    const int rowB = (lane & 7) + ((lane >> 4) & 1) * 8;
    const int colB = ((lane >> 3) & 1) * 8;

    const int nk = K >> 5;

    {
        cp_tile(sb + OAH, Ahb, lda, m0, 0, tid);
        if (PASSES >= 2) cp_tile(sb + OAL, Alb, lda, m0, 0, tid);
        cp_tile(sb + OBH, Bhb, ldb, n0, 0, tid);
        if (PASSES == 3) cp_tile(sb + OBL, Blb, ldb, n0, 0, tid);
        CP_COMMIT();
    }

    for (int kt = 0; kt < nk; kt++) {
        if (kt + 1 < nk) {
            uint32_t s1 = sb + ((kt + 1) & 1) * STG;
            int k0 = (kt + 1) << 5;
            cp_tile(s1 + OAH, Ahb, lda, m0, k0, tid);
            if (PASSES >= 2) cp_tile(s1 + OAL, Alb, lda, m0, k0, tid);
            cp_tile(s1 + OBH, Bhb, ldb, n0, k0, tid);
            if (PASSES == 3) cp_tile(s1 + OBL, Blb, ldb, n0, k0, tid);
            CP_COMMIT();
            CP_WAIT(1);
        } else {
            CP_WAIT(0);
        }
        __syncthreads();

        uint32_t s0 = sb + (kt & 1) * STG;
#pragma unroll
        for (int ks = 0; ks < 2; ks++) {
            uint32_t ah[2][4], al[2][4], bh[4][4], bl[4][4];
#pragma unroll
            for (int mi = 0; mi < 2; mi++) {
                uint32_t off = (uint32_t)((wm * 32 + mi * 16 + rowA) * 80 +
                                          (ks * 16 + colA) * 2);
                ldm4(ah[mi], s0 + OAH + off);
                if (PASSES >= 2) ldm4(al[mi], s0 + OAL + off);
            }
#pragma unroll
            for (int nj = 0; nj < 4; nj++) {
                uint32_t off = (uint32_t)((wn * 64 + nj * 16 + rowB) * 80 +
                                          (ks * 16 + colB) * 2);
                ldm4(bh[nj], s0 + OBH + off);
                if (PASSES == 3) ldm4(bl[nj], s0 + OBL + off);
            }
#pragma unroll
            for (int mi = 0; mi < 2; mi++)
#pragma unroll
                for (int nj = 0; nj < 4; nj++)
#pragma unroll
                    for (int sub = 0; sub < 2; sub++) {
                        float* d = acc[mi][nj * 2 + sub];
                        mma16816(d, ah[mi], &bh[nj][sub * 2]);
                        if (PASSES >= 2) mma16816(d, al[mi], &bh[nj][sub * 2]);
                        if (PASSES == 3) mma16816(d, ah[mi], &bl[nj][sub * 2]);
                    }
        }
        __syncthreads();
    }

    // epilogue
    const bool wantLo = (EPI == 1) && (bz < loBz);
#pragma unroll
    for (int mi = 0; mi < 2; mi++) {
        int rbase = m0 + wm * 32 + mi * 16 + (lane >> 2);
#pragma unroll
        for (int nj = 0; nj < 8; nj++) {
            int c0 = n0 + wn * 64 + nj * 8 + (lane & 3) * 2;
            float* d = acc[mi][nj];
#pragma unroll
            for (int hr = 0; hr < 2; hr++) {
                int r = rbase + hr * 8;
                float v0 = d[hr * 2 + 0];
                float v1 = d[hr * 2 + 1];
                if (EPI == 0) {
                    *reinterpret_cast<float2*>(&C[(size_t)bz * sC + (size_t)r * ldc + c0]) =
                        make_float2(v0, v1);
                } else if (EPI == 3) {
                    float rb = bias[(size_t)bz * sBias + r];
                    v0 += rb;
                    v1 += rb;
                    size_t o = (size_t)bz * sC + (size_t)r * ldc + c0;
                    *reinterpret_cast<__half2*>(&Oh[o]) =
                        __halves2half2(__float2half_rn(v0), __float2half_rn(v1));
                } else {
                    if (bias) {
                        v0 += bias[(size_t)bz * sBias + c0];
                        v1 += bias[(size_t)bz * sBias + c0 + 1];
                    }
                    if (EPI == 2) {
                        v0 = 0.5f * v0 * (1.0f + erff(v0 * 0.70710678118654752f));
                        v1 = 0.5f * v1 * (1.0f + erff(v1 * 0.70710678118654752f));
                    }
                    h16 h0 = __float2half_rn(v0), h1 = __float2half_rn(v1);
                    size_t o = (size_t)bz * sC + (size_t)r * ldc + c0;
                    *reinterpret_cast<__half2*>(&Oh[o]) = __halves2half2(h0, h1);
                    if (EPI == 2 || wantLo) {
                        *reinterpret_cast<__half2*>(&Ol[o]) = __halves2half2(
                            __float2half_rn(v0 - __half2float(h0)),
                            __float2half_rn(v1 - __half2float(h1)));
                    }
                }
            }
        }
    }
}

// ---------------- split-K reduce: out = p0 + p1 + bias + resid (fp32) ----------------
__global__ void reduce2_bias_resid(const float* __restrict__ p, const float* __restrict__ bias,
                                   const float* __restrict__ resid, float* __restrict__ out) {
    size_t i = (size_t)blockIdx.x * 256 + threadIdx.x;
    out[i] = p[i] + p[i + (size_t)Nn * Dd] + bias[i & (Dd - 1)] + resid[i];
}

// ---------------- fused: x1 = p0+p1+bo+x ; h2 = LN(x1) -> fp16 hi/lo ----------------
__global__ void reduce2_ln_split(const float* __restrict__ p, const float* __restrict__ bias,
                                 const float* __restrict__ resid, const float* __restrict__ g,
                                 const float* __restrict__ beta, float* __restrict__ x1,
                                 h16* __restrict__ oh, h16* __restrict__ ol) {
    int row = blockIdx.x;
    int tid = threadIdx.x;  // 128
    size_t base = (size_t)row * Dd;
    float v[4];
    float s = 0.f;
#pragma unroll
    for (int i = 0; i < 4; i++) {
        int c = tid + i * 128;
        float t = p[base + c] + p[base + c + (size_t)Nn * Dd] + bias[c] + resid[base + c];
        v[i] = t;
        x1[base + c] = t;
        s += t;
    }
    __shared__ float red[4];
#pragma unroll
    for (int o = 16; o; o >>= 1) s += __shfl_xor_sync(0xffffffffu, s, o);
    if ((tid & 31) == 0) red[tid >> 5] = s;
    __syncthreads();
    float mu = (red[0] + red[1] + red[2] + red[3]) * (1.f / 512.f);
    float vs = 0.f;
#pragma unroll
    for (int i = 0; i < 4; i++) { float t = v[i] - mu; vs += t * t; }
#pragma unroll
    for (int o = 16; o; o >>= 1) vs += __shfl_xor_sync(0xffffffffu, vs, o);
    __syncthreads();
    if ((tid & 31) == 0) red[tid >> 5] = vs;
    __syncthreads();
    float var = (red[0] + red[1] + red[2] + red[3]) * (1.f / 512.f);
    float rstd = rsqrtf(var + 1e-5f);
#pragma unroll
    for (int i = 0; i < 4; i++) {
        int c = tid + i * 128;
        float o = (v[i] - mu) * rstd * g[c] + beta[c];
        split_h(o, oh, ol, base + c);
    }
}

// ---------------- weight prep: fp32 [R][C] -> fp16 [C][R] hi, scaled ----------------
__global__ void transpose_w(const float* __restrict__ in, h16* __restrict__ oh,
                            int R, int C, float scale) {
    __shared__ float t[32][33];
    int bz = blockIdx.z;
    size_t oz = (size_t)bz * R * C;
    int c0 = blockIdx.x * 32, r0 = blockIdx.y * 32;
    int tx = threadIdx.x, ty = threadIdx.y;  // (32,8)
#pragma unroll
    for (int k = 0; k < 4; k++) {
        int r = r0 + ty + k * 8;
        t[ty + k * 8][tx] = in[(size_t)bz * R * C + (size_t)r * C + c0 + tx] * scale;
    }
    __syncthreads();
#pragma unroll
    for (int k = 0; k < 4; k++) {
        int c = c0 + ty + k * 8;
        oh[oz + (size_t)c * R + r0 + tx] = __float2half_rn(t[tx][ty + k * 8]);
    }
}

// ---------------- pack QKV biases (scale folded into Q) ----------------
__global__ void pack_bias(const float* __restrict__ bq, const float* __restrict__ bk,
                          const float* __restrict__ bv, float* __restrict__ o, float s) {
    int i = blockIdx.x * 256 + threadIdx.x;  // 24*512
    int z = i >> 9, c = i & 511;
    float v = (z < 8) ? bq[z * 512 + c] * s
                      : ((z < 16) ? bk[(z - 8) * 512 + c] : bv[(z - 16) * 512 + c]);
    o[i] = v;
}

// ---------------- layernorm(512) -> fp16 hi only ----------------
__global__ void layernorm512_h(const float* __restrict__ x, const float* __restrict__ g,
                               const float* __restrict__ beta, h16* __restrict__ oh) {
    int row = blockIdx.x;
    const float* xr = x + (size_t)row * Dd;
    int tid = threadIdx.x;  // 128
    float v[4];
    float s = 0.f;
#pragma unroll
    for (int i = 0; i < 4; i++) { v[i] = xr[tid + i * 128]; s += v[i]; }
    __shared__ float red[4];
#pragma unroll
    for (int o = 16; o; o >>= 1) s += __shfl_xor_sync(0xffffffffu, s, o);
    if ((tid & 31) == 0) red[tid >> 5] = s;
    __syncthreads();
    float mu = (red[0] + red[1] + red[2] + red[3]) * (1.f / 512.f);
    float vs = 0.f;
#pragma unroll
    for (int i = 0; i < 4; i++) { float t = v[i] - mu; vs += t * t; }
#pragma unroll
    for (int o = 16; o; o >>= 1) vs += __shfl_xor_sync(0xffffffffu, vs, o);
    __syncthreads();
    if ((tid & 31) == 0) red[tid >> 5] = vs;
    __syncthreads();
    float var = (red[0] + red[1] + red[2] + red[3]) * (1.f / 512.f);
    float rstd = rsqrtf(var + 1e-5f);
#pragma unroll
    for (int i = 0; i < 4; i++) {
        int c = tid + i * 128;
        oh[(size_t)row * Dd + c] = __float2half_rn((v[i] - mu) * rstd * g[c] + beta[c]);
    }
}

// ---------------- edge dot ----------------
__global__ void edge_d_kernel(const float* __restrict__ edge_attr,
                              const float* __restrict__ edge_vec,
                              float* __restrict__ dout) {
    __shared__ float ea[4][EDd];
    int e0 = blockIdx.x * 4;
    int tid = threadIdx.x;
    for (int i = tid; i < 4 * EDd; i += 128)
        ea[i >> 6][i & 63] = edge_attr[(size_t)e0 * EDd + i];
    __syncthreads();
    int el = tid >> 5;
    int hp = tid & 31;
    const float* ev = edge_vec + hp * EDd;
    float s = 0.f;
#pragma unroll
    for (int f = 0; f < EDd; f++) s += ea[el][f] * ev[f];
    int h = hp >> 2, p = hp & 3;
    dout[((size_t)h * Ee + (e0 + el)) * Pp + p] = s;
}

// ---------------- fused bias(b) + path-bias + softmax -> fp16 hi only ----------------
__global__ void bias_c_softmax(const float* __restrict__ S, const float* __restrict__ b,
                               const int* __restrict__ path_idx,
                               const int* __restrict__ path_len,
                               const float* __restrict__ dmat,
                               h16* __restrict__ Sh) {
    int h = blockIdx.x;
    int row = blockIdx.y;
    const float* r = S + ((size_t)h * Nn + row) * Nn;
    const float* br = b + (size_t)row * Nn;
    const int* plr = path_len + (size_t)row * Nn;
    const int* pir = path_idx + (size_t)row * Nn * Pp;
    const float* dh = dmat + (size_t)h * Ee * Pp;
    int tid = threadIdx.x;  // 256
    float v[8];
    float m = -1e30f;
#pragma unroll
    for (int i = 0; i < 8; i++) {
        int col = tid + i * 256;
        int pl = plr[col];
        float c = 0.f;
        if (pl > 0) {
            const int4 pi = *reinterpret_cast<const int4*>(pir + (size_t)col * 4);
            float s = dh[(size_t)pi.x * 4 + 0];
            if (1 < pl) s += dh[(size_t)pi.y * 4 + 1];
            if (2 < pl) s += dh[(size_t)pi.z * 4 + 2];
            if (3 < pl) s += dh[(size_t)pi.w * 4 + 3];
            c = s / (float)pl;
        }
        v[i] = r[col] + br[col] + c;
        m = fmaxf(m, v[i]);
    }
    __shared__ float red[8];
#pragma unroll
    for (int o = 16; o; o >>= 1) m = fmaxf(m, __shfl_xor_sync(0xffffffffu, m, o));
    if ((tid & 31) == 0) red[tid >> 5] = m;
    __syncthreads();
    m = red[0];
#pragma unroll
    for (int i = 1; i < 8; i++) m = fmaxf(m, red[i]);
    float s = 0.f;
#pragma unroll
    for (int i = 0; i < 8; i++) { v[i] = __expf(v[i] - m); s += v[i]; }
#pragma unroll
    for (int o = 16; o; o >>= 1) s += __shfl_xor_sync(0xffffffffu, s, o);
    __syncthreads();
    if ((tid & 31) == 0) red[tid >> 5] = s;
    __syncthreads();
    s = red[0];
#pragma unroll
    for (int i = 1; i < 8; i++) s += red[i];
    float inv = 1.f / s;
    size_t base = ((size_t)h * Nn + row) * Nn;
#pragma unroll
    for (int i = 0; i < 8; i++)
        Sh[base + tid + i * 256] = __float2half_rn(v[i] * inv);
}

// ---------------- host ----------------
#define GETSYM(var, sym) cudaGetSymbolAddress((void**)&var, sym)

extern "C" void kernel_launch(void* const* d_in, const int* in_sizes, int n_in,
                              void* d_out, int out_size) {
    const float* x         = (const float*)d_in[0];
    const float* edge_attr = (const float*)d_in[1];
    const float* b         = (const float*)d_in[2];
    const int*   path_idx  = (const int*)d_in[3];
    const int*   path_len  = (const int*)d_in[4];
    const float* Wq        = (const float*)d_in[5];
    const float* bq        = (const float*)d_in[6];
    const float* Wk        = (const float*)d_in[7];
    const float* bk        = (const float*)d_in[8];
    const float* Wv        = (const float*)d_in[9];
    const float* bv        = (const float*)d_in[10];
    const float* edge_vec  = (const float*)d_in[11];
    const float* Wo        = (const float*)d_in[12];
    const float* bo        = (const float*)d_in[13];
    const float* ln1_g     = (const float*)d_in[14];
    const float* ln1_b     = (const float*)d_in[15];
    const float* ln2_g     = (const float*)d_in[16];
    const float* ln2_b     = (const float*)d_in[17];
    const float* W1        = (const float*)d_in[18];
    const float* b1        = (const float*)d_in[19];
    const float* W2        = (const float*)d_in[20];
    const float* b2        = (const float*)d_in[21];
    float* out = (float*)d_out;

    float *Sf, *x1f, *dmat, *bqkv;
    GETSYM(Sf, g_Sf); GETSYM(x1f, g_x1); GETSYM(dmat, g_dmat); GETSYM(bqkv, g_bqkv);
    h16 *xh, *QKVh, *Vth, *Sh, *mhh, *h2h, *h2l, *ffh, *ffl;
    h16 *Wh, *Woh, *W1h, *W2h;
    GETSYM(xh, g_xh);
    GETSYM(QKVh, g_QKVh);
    GETSYM(Vth, g_Vth);
    GETSYM(Sh, g_Sh);
    GETSYM(mhh, g_mhh);
    GETSYM(h2h, g_h2h); GETSYM(h2l, g_h2l);
    GETSYM(ffh, g_ffh); GETSYM(ffl, g_ffl);
    GETSYM(Wh, g_Wh);
    GETSYM(Woh, g_Woh);
    GETSYM(W1h, g_W1h);
    GETSYM(W2h, g_W2h);

    const int SM1 = 40960;
    const int SM2 = 61440;
    cudaFuncSetAttribute(gemm_h<1, 0, 2>, cudaFuncAttributeMaxDynamicSharedMemorySize, SM1);
    cudaFuncSetAttribute(gemm_h<1, 1, 2>, cudaFuncAttributeMaxDynamicSharedMemorySize, SM1);
    cudaFuncSetAttribute(gemm_h<1, 3, 2>, cudaFuncAttributeMaxDynamicSharedMemorySize, SM1);
    cudaFuncSetAttribute(gemm_h<2, 0, 2>, cudaFuncAttributeMaxDynamicSharedMemorySize, SM2);
    cudaFuncSetAttribute(gemm_h<2, 2, 2>, cudaFuncAttributeMaxDynamicSharedMemorySize, SM2);

    const float scale = 1.0f / sqrtf((float)Dd);
    dim3 tb32(32, 8);
    const long ND = (long)Nn * Dd;
    const long NN = (long)Nn * Nn;
    const long DD = (long)Dd * Dd;

    // weight prep (transpose to K-major fp16, hi only everywhere)
    transpose_w<<<dim3(16, 16, Hh), tb32>>>(Wq, Wh, Dd, Dd, scale);
    transpose_w<<<dim3(16, 16, Hh), tb32>>>(Wk, Wh + 8 * DD, Dd, Dd, 1.f);
    transpose_w<<<dim3(16, 16, Hh), tb32>>>(Wv, Wh + 16 * DD, Dd, Dd, 1.f);
    transpose_w<<<dim3(16, 128, 1), tb32>>>(Wo, Woh, Hh * Dd, Dd, 1.f);
    transpose_w<<<dim3(64, 16, 1), tb32>>>(W1, W1h, Dd, Ff, 1.f);
    transpose_w<<<dim3(16, 64, 1), tb32>>>(W2, W2h, Ff, Dd, 1.f);
    pack_bias<<<48, 256>>>(bq, bk, bv, bqkv, scale);

    // LN1 (hi only), edge dots
    layernorm512_h<<<Nn, 128>>>(x, ln1_g, ln1_b, xh);
    edge_d_kernel<<<Ee / 4, 128>>>(edge_attr, edge_vec, dmat);

    // Q/K: batched 1-pass GEMM (16 batches), epilogue = +bias, hi out only
    gemm_h<1, 1, 2><<<dim3(4, 16, 16), 256, SM1>>>(
        xh, nullptr, Wh, nullptr, nullptr, QKVh, nullptr, bqkv,
        Dd, Dd, Dd, Dd, 0, DD, ND, Dd, 0);

    // V^T directly: Vt[h][d][n] = sum_k Wv[h][k][d]*xln[n][k] + bv[h][d]
    gemm_h<1, 3, 2><<<dim3(16, 4, Hh), 256, SM1>>>(
        Wh + 16 * DD, nullptr, xh, nullptr, nullptr, Vth, nullptr, bv,
        Dd, Dd, Dd, Nn, DD, 0, (long)Dd * Nn, Dd, 0);

    // scores: S[h] = Qs @ K^T (1-pass, fp32 out)
    gemm_h<1, 0, 2><<<dim3(16, 16, Hh), 256, SM1>>>(
        QKVh, nullptr, QKVh + 8 * ND, nullptr, Sf, nullptr, nullptr, nullptr,
        Dd, Dd, Dd, Nn, ND, ND, NN, 0, 0);

    // spatial + path bias, softmax -> fp16 hi only
    bias_c_softmax<<<dim3(Hh, Nn), 256>>>(Sf, b, path_idx, path_len, dmat, Sh);

    // attn @ V -> mh (1-pass, hi out only)
    gemm_h<1, 1, 2><<<dim3(4, 16, Hh), 256, SM1>>>(
        Sh, nullptr, Vth, nullptr, nullptr, mhh, nullptr, nullptr,
        Nn, Nn, Nn, Hh * Dd, NN, (long)Dd * Nn, Dd, 0, 0);

    // x1 = mh @ Wo + bo + x  (1-pass now, split-K=2 -> partials in Sf, fused reduce+LN2)
    gemm_h<1, 0, 2><<<dim3(4, 16, 2), 256, SM1>>>(
        mhh, nullptr, Woh, nullptr, Sf, nullptr, nullptr, nullptr,
        Hh * Dd / 2, Hh * Dd, Hh * Dd, Dd, Hh * Dd / 2, Hh * Dd / 2, ND, 0, 0);
    reduce2_ln_split<<<Nn, 128>>>(Sf, bo, x, ln2_g, ln2_b, x1f, h2h, h2l);

    // ff = gelu(h2 @ W1 + b1) (2-pass: A split, W1 hi only; fused gelu+split)
    gemm_h<2, 2, 2><<<dim3(16, 16, 1), 256, SM2>>>(
        h2h, h2l, W1h, nullptr, nullptr, ffh, ffl, b1,
        Dd, Dd, Dd, Ff, 0, 0, 0, 0, 0);

    // out = ff @ W2 + b2 + x1 (2-pass: A split, W2 hi only; split-K=2 -> reduce)
    gemm_h<2, 0, 2><<<dim3(4, 16, 2), 256, SM2>>>(
        ffh, ffl, W2h, nullptr, Sf, nullptr, nullptr, nullptr,
        Ff / 2, Ff, Ff, Dd, Ff / 2, Ff / 2, ND, 0, 0);
    reduce2_bias_resid<<<(Nn * Dd) / 256, 256>>>(Sf, b2, x1f, out);
}

// round 17
// speedup vs baseline: 1.2892x; 1.0280x over previous
#include <cuda_runtime.h>
#include <cuda_fp16.h>
#include <math.h>
#include <stdint.h>

#define Nn 2048
#define Dd 512
#define Hh 8
#define Ff 2048
#define EDd 64
#define Pp 4
#define Ee 32768

typedef __half h16;

// ---------------- static scratch (no allocations allowed) ----------------
__device__ float g_Sf[(size_t)Hh * Nn * Nn];      // 128 MB scores (+ split-K partials reuse)
__device__ float g_x1[Nn * Dd];
__device__ float g_dmat[Hh * Ee * Pp];
__device__ float g_bqkv[24 * Dd];

__device__ h16 g_xh[Nn * Dd];
__device__ h16 g_QKVh[16 * Nn * Dd];                         // Q:0-7 K:8-15 (hi only)
__device__ h16 g_Vth[(size_t)Hh * Dd * Nn];                  // V^T computed directly
__device__ h16 g_Sh[(size_t)Hh * Nn * Nn];                   // softmax probs, hi only
__device__ h16 g_mhh[(size_t)Nn * Hh * Dd];
__device__ h16 g_h2h[Nn * Dd];
__device__ h16 g_ffh[Nn * Ff];
__device__ h16 g_Wh[24 * Dd * Dd];                            // QKV weights (transposed), hi only
__device__ h16 g_Woh[Dd * Hh * Dd];
__device__ h16 g_W1h[Ff * Dd];
__device__ h16 g_W2h[Dd * Ff];

// ---------------- low-level helpers ----------------
__device__ __forceinline__ uint32_t smem_u32(const void* p) {
    uint32_t a;
    asm("{ .reg .u64 t; cvta.to.shared.u64 t, %1; cvt.u32.u64 %0, t; }" : "=r"(a) : "l"(p));
    return a;
}
__device__ __forceinline__ void ldm4(uint32_t* r, uint32_t addr) {
    asm volatile("ldmatrix.sync.aligned.m8n8.x4.shared.b16 {%0,%1,%2,%3}, [%4];"
                 : "=r"(r[0]), "=r"(r[1]), "=r"(r[2]), "=r"(r[3]) : "r"(addr));
}
__device__ __forceinline__ void mma16816(float* d, const uint32_t* a, const uint32_t* b) {
    asm volatile(
        "mma.sync.aligned.m16n8k16.row.col.f32.f16.f16.f32 "
        "{%0,%1,%2,%3}, {%4,%5,%6,%7}, {%8,%9}, {%0,%1,%2,%3};"
        : "+f"(d[0]), "+f"(d[1]), "+f"(d[2]), "+f"(d[3])
        : "r"(a[0]), "r"(a[1]), "r"(a[2]), "r"(a[3]), "r"(b[0]), "r"(b[1]));
}
__device__ __forceinline__ void cp16(uint32_t sdst, const void* gsrc) {
    asm volatile("cp.async.cg.shared.global [%0], [%1], 16;" :: "r"(sdst), "l"(gsrc));
}
#define CP_COMMIT() asm volatile("cp.async.commit_group;" ::: "memory")
#define CP_WAIT(n)  asm volatile("cp.async.wait_group %0;" :: "n"(n) : "memory")

// one 128x32 fp16 tile (row-major, leading dim ld) into 80B-pitched smem
__device__ __forceinline__ void cp_tile(uint32_t sdst, const h16* __restrict__ src,
                                        int ld, int row0, int k0, int tid) {
#pragma unroll
    for (int it = 0; it < 2; it++) {
        int idx = tid + it * 256;
        int r = idx >> 2, c = idx & 3;
        cp16(sdst + r * 80 + c * 16, src + (size_t)(row0 + r) * ld + k0 + c * 8);
    }
}

// ---------------- fp16 mma.sync GEMM: acc[M,N] = sum_k A[m,k]*B[n,k]  (1-pass hi*hi) ----
// CTA tile 128x128, 8 warps in 4(M)x2(N), 32x64 per warp, occupancy 2.
// EPI: 0 = fp32 C (also split-K partials); 1 = (acc + colbias) -> Oh fp16;
//      2 = gelu(acc + colbias) -> Oh fp16; 3 = (acc + rowbias[m]) -> Oh fp16.
template <int EPI>
__global__ void __launch_bounds__(256, 2)
gemm_h(const h16* __restrict__ Ah_, const h16* __restrict__ Bh_,
       float* __restrict__ C, h16* __restrict__ Oh,
       const float* __restrict__ bias,
       int K, int lda, int ldb, int ldc,
       long sA, long sB, long sC, long sBias) {
    constexpr int STG = 2 * 10240;
    constexpr int OAH = 0;
    constexpr int OBH = 10240;
    extern __shared__ char smem[];
    const int tid = threadIdx.x;
    const int lane = tid & 31;
    const int wid = tid >> 5;
    const int wm = wid & 3;
    const int wn = wid >> 2;
    const int bz = blockIdx.z;
    const h16* Ahb = Ah_ + (size_t)bz * sA;
    const h16* Bhb = Bh_ + (size_t)bz * sB;
    const int m0 = blockIdx.y * 128;
    const int n0 = blockIdx.x * 128;
    const uint32_t sb = smem_u32(smem);

    float acc[2][8][4];
#pragma unroll
    for (int i = 0; i < 2; i++)
#pragma unroll
        for (int j = 0; j < 8; j++)
#pragma unroll
            for (int t = 0; t < 4; t++) acc[i][j][t] = 0.f;

    const int rowA = (lane & 15);
    const int colA = (lane >> 4) * 8;
    const int rowB = (lane & 7) + ((lane >> 4) & 1) * 8;
    const int colB = ((lane >> 3) & 1) * 8;

    const int nk = K >> 5;

    {
        cp_tile(sb + OAH, Ahb, lda, m0, 0, tid);
        cp_tile(sb + OBH, Bhb, ldb, n0, 0, tid);
        CP_COMMIT();
    }

    for (int kt = 0; kt < nk; kt++) {
        if (kt + 1 < nk) {
            uint32_t s1 = sb + ((kt + 1) & 1) * STG;
            int k0 = (kt + 1) << 5;
            cp_tile(s1 + OAH, Ahb, lda, m0, k0, tid);
            cp_tile(s1 + OBH, Bhb, ldb, n0, k0, tid);
            CP_COMMIT();
            CP_WAIT(1);
        } else {
            CP_WAIT(0);
        }
        __syncthreads();

        uint32_t s0 = sb + (kt & 1) * STG;
#pragma unroll
        for (int ks = 0; ks < 2; ks++) {
            uint32_t ah[2][4], bh[4][4];
#pragma unroll
            for (int mi = 0; mi < 2; mi++) {
                uint32_t off = (uint32_t)((wm * 32 + mi * 16 + rowA) * 80 +
                                          (ks * 16 + colA) * 2);
                ldm4(ah[mi], s0 + OAH + off);
            }
#pragma unroll
            for (int nj = 0; nj < 4; nj++) {
                uint32_t off = (uint32_t)((wn * 64 + nj * 16 + rowB) * 80 +
                                          (ks * 16 + colB) * 2);
                ldm4(bh[nj], s0 + OBH + off);
            }
#pragma unroll
            for (int mi = 0; mi < 2; mi++)
#pragma unroll
                for (int nj = 0; nj < 4; nj++)
#pragma unroll
                    for (int sub = 0; sub < 2; sub++)
                        mma16816(acc[mi][nj * 2 + sub], ah[mi], &bh[nj][sub * 2]);
        }
        __syncthreads();
    }

    // epilogue
#pragma unroll
    for (int mi = 0; mi < 2; mi++) {
        int rbase = m0 + wm * 32 + mi * 16 + (lane >> 2);
#pragma unroll
        for (int nj = 0; nj < 8; nj++) {
            int c0 = n0 + wn * 64 + nj * 8 + (lane & 3) * 2;
            float* d = acc[mi][nj];
#pragma unroll
            for (int hr = 0; hr < 2; hr++) {
                int r = rbase + hr * 8;
                float v0 = d[hr * 2 + 0];
                float v1 = d[hr * 2 + 1];
                if (EPI == 0) {
                    *reinterpret_cast<float2*>(&C[(size_t)bz * sC + (size_t)r * ldc + c0]) =
                        make_float2(v0, v1);
                } else if (EPI == 3) {
                    float rb = bias[(size_t)bz * sBias + r];
                    v0 += rb;
                    v1 += rb;
                    size_t o = (size_t)bz * sC + (size_t)r * ldc + c0;
                    *reinterpret_cast<__half2*>(&Oh[o]) =
                        __halves2half2(__float2half_rn(v0), __float2half_rn(v1));
                } else {
                    if (bias) {
                        v0 += bias[(size_t)bz * sBias + c0];
                        v1 += bias[(size_t)bz * sBias + c0 + 1];
                    }
                    if (EPI == 2) {
                        v0 = 0.5f * v0 * (1.0f + erff(v0 * 0.70710678118654752f));
                        v1 = 0.5f * v1 * (1.0f + erff(v1 * 0.70710678118654752f));
                    }
                    size_t o = (size_t)bz * sC + (size_t)r * ldc + c0;
                    *reinterpret_cast<__half2*>(&Oh[o]) =
                        __halves2half2(__float2half_rn(v0), __float2half_rn(v1));
                }
            }
        }
    }
}

// ---------------- split-K reduce: out = p0 + p1 + bias + resid (fp32) ----------------
__global__ void reduce2_bias_resid(const float* __restrict__ p, const float* __restrict__ bias,
                                   const float* __restrict__ resid, float* __restrict__ out) {
    size_t i = (size_t)blockIdx.x * 256 + threadIdx.x;
    out[i] = p[i] + p[i + (size_t)Nn * Dd] + bias[i & (Dd - 1)] + resid[i];
}

// ---------------- fused: x1 = p0+p1+bo+x ; h2 = LN(x1) -> fp16 hi ----------------
__global__ void reduce2_ln_h(const float* __restrict__ p, const float* __restrict__ bias,
                             const float* __restrict__ resid, const float* __restrict__ g,
                             const float* __restrict__ beta, float* __restrict__ x1,
                             h16* __restrict__ oh) {
    int row = blockIdx.x;
    int tid = threadIdx.x;  // 128
    size_t base = (size_t)row * Dd;
    float v[4];
    float s = 0.f;
#pragma unroll
    for (int i = 0; i < 4; i++) {
        int c = tid + i * 128;
        float t = p[base + c] + p[base + c + (size_t)Nn * Dd] + bias[c] + resid[base + c];
        v[i] = t;
        x1[base + c] = t;
        s += t;
    }
    __shared__ float red[4];
#pragma unroll
    for (int o = 16; o; o >>= 1) s += __shfl_xor_sync(0xffffffffu, s, o);
    if ((tid & 31) == 0) red[tid >> 5] = s;
    __syncthreads();
    float mu = (red[0] + red[1] + red[2] + red[3]) * (1.f / 512.f);
    float vs = 0.f;
#pragma unroll
    for (int i = 0; i < 4; i++) { float t = v[i] - mu; vs += t * t; }
#pragma unroll
    for (int o = 16; o; o >>= 1) vs += __shfl_xor_sync(0xffffffffu, vs, o);
    __syncthreads();
    if ((tid & 31) == 0) red[tid >> 5] = vs;
    __syncthreads();
    float var = (red[0] + red[1] + red[2] + red[3]) * (1.f / 512.f);
    float rstd = rsqrtf(var + 1e-5f);
#pragma unroll
    for (int i = 0; i < 4; i++) {
        int c = tid + i * 128;
        oh[base + c] = __float2half_rn((v[i] - mu) * rstd * g[c] + beta[c]);
    }
}

// ---------------- weight prep: fp32 [R][C] -> fp16 [C][R] hi, scaled ----------------
__global__ void transpose_w(const float* __restrict__ in, h16* __restrict__ oh,
                            int R, int C, float scale) {
    __shared__ float t[32][33];
    int bz = blockIdx.z;
    size_t oz = (size_t)bz * R * C;
    int c0 = blockIdx.x * 32, r0 = blockIdx.y * 32;
    int tx = threadIdx.x, ty = threadIdx.y;  // (32,8)
#pragma unroll
    for (int k = 0; k < 4; k++) {
        int r = r0 + ty + k * 8;
        t[ty + k * 8][tx] = in[(size_t)bz * R * C + (size_t)r * C + c0 + tx] * scale;
    }
    __syncthreads();
#pragma unroll
    for (int k = 0; k < 4; k++) {
        int c = c0 + ty + k * 8;
        oh[oz + (size_t)c * R + r0 + tx] = __float2half_rn(t[tx][ty + k * 8]);
    }
}

// ---------------- pack QKV biases (scale folded into Q) ----------------
__global__ void pack_bias(const float* __restrict__ bq, const float* __restrict__ bk,
                          const float* __restrict__ bv, float* __restrict__ o, float s) {
    int i = blockIdx.x * 256 + threadIdx.x;  // 24*512
    int z = i >> 9, c = i & 511;
    float v = (z < 8) ? bq[z * 512 + c] * s
                      : ((z < 16) ? bk[(z - 8) * 512 + c] : bv[(z - 16) * 512 + c]);
    o[i] = v;
}

// ---------------- layernorm(512) -> fp16 hi only ----------------
__global__ void layernorm512_h(const float* __restrict__ x, const float* __restrict__ g,
                               const float* __restrict__ beta, h16* __restrict__ oh) {
    int row = blockIdx.x;
    const float* xr = x + (size_t)row * Dd;
    int tid = threadIdx.x;  // 128
    float v[4];
    float s = 0.f;
#pragma unroll
    for (int i = 0; i < 4; i++) { v[i] = xr[tid + i * 128]; s += v[i]; }
    __shared__ float red[4];
#pragma unroll
    for (int o = 16; o; o >>= 1) s += __shfl_xor_sync(0xffffffffu, s, o);
    if ((tid & 31) == 0) red[tid >> 5] = s;
    __syncthreads();
    float mu = (red[0] + red[1] + red[2] + red[3]) * (1.f / 512.f);
    float vs = 0.f;
#pragma unroll
    for (int i = 0; i < 4; i++) { float t = v[i] - mu; vs += t * t; }
#pragma unroll
    for (int o = 16; o; o >>= 1) vs += __shfl_xor_sync(0xffffffffu, vs, o);
    __syncthreads();
    if ((tid & 31) == 0) red[tid >> 5] = vs;
    __syncthreads();
    float var = (red[0] + red[1] + red[2] + red[3]) * (1.f / 512.f);
    float rstd = rsqrtf(var + 1e-5f);
#pragma unroll
    for (int i = 0; i < 4; i++) {
        int c = tid + i * 128;
        oh[(size_t)row * Dd + c] = __float2half_rn((v[i] - mu) * rstd * g[c] + beta[c]);
    }
}

// ---------------- edge dot ----------------
__global__ void edge_d_kernel(const float* __restrict__ edge_attr,
                              const float* __restrict__ edge_vec,
                              float* __restrict__ dout) {
    __shared__ float ea[4][EDd];
    int e0 = blockIdx.x * 4;
    int tid = threadIdx.x;
    for (int i = tid; i < 4 * EDd; i += 128)
        ea[i >> 6][i & 63] = edge_attr[(size_t)e0 * EDd + i];
    __syncthreads();
    int el = tid >> 5;
    int hp = tid & 31;
    const float* ev = edge_vec + hp * EDd;
    float s = 0.f;
#pragma unroll
    for (int f = 0; f < EDd; f++) s += ea[el][f] * ev[f];
    int h = hp >> 2, p = hp & 3;
    dout[((size_t)h * Ee + (e0 + el)) * Pp + p] = s;
}

// ---------------- fused bias(b) + path-bias + softmax -> fp16 hi only ----------------
__global__ void bias_c_softmax(const float* __restrict__ S, const float* __restrict__ b,
                               const int* __restrict__ path_idx,
                               const int* __restrict__ path_len,
                               const float* __restrict__ dmat,
                               h16* __restrict__ Sh) {
    int h = blockIdx.x;
    int row = blockIdx.y;
    const float* r = S + ((size_t)h * Nn + row) * Nn;
    const float* br = b + (size_t)row * Nn;
    const int* plr = path_len + (size_t)row * Nn;
    const int* pir = path_idx + (size_t)row * Nn * Pp;
    const float* dh = dmat + (size_t)h * Ee * Pp;
    int tid = threadIdx.x;  // 256
    float v[8];
    float m = -1e30f;
#pragma unroll
    for (int i = 0; i < 8; i++) {
        int col = tid + i * 256;
        int pl = plr[col];
        float c = 0.f;
        if (pl > 0) {
            const int4 pi = *reinterpret_cast<const int4*>(pir + (size_t)col * 4);
            float s = dh[(size_t)pi.x * 4 + 0];
            if (1 < pl) s += dh[(size_t)pi.y * 4 + 1];
            if (2 < pl) s += dh[(size_t)pi.z * 4 + 2];
            if (3 < pl) s += dh[(size_t)pi.w * 4 + 3];
            c = s / (float)pl;
        }
        v[i] = r[col] + br[col] + c;
        m = fmaxf(m, v[i]);
    }
    __shared__ float red[8];
#pragma unroll
    for (int o = 16; o; o >>= 1) m = fmaxf(m, __shfl_xor_sync(0xffffffffu, m, o));
    if ((tid & 31) == 0) red[tid >> 5] = m;
    __syncthreads();
    m = red[0];
#pragma unroll
    for (int i = 1; i < 8; i++) m = fmaxf(m, red[i]);
    float s = 0.f;
#pragma unroll
    for (int i = 0; i < 8; i++) { v[i] = __expf(v[i] - m); s += v[i]; }
#pragma unroll
    for (int o = 16; o; o >>= 1) s += __shfl_xor_sync(0xffffffffu, s, o);
    __syncthreads();
    if ((tid & 31) == 0) red[tid >> 5] = s;
    __syncthreads();
    s = red[0];
#pragma unroll
    for (int i = 1; i < 8; i++) s += red[i];
    float inv = 1.f / s;
    size_t base = ((size_t)h * Nn + row) * Nn;
#pragma unroll
    for (int i = 0; i < 8; i++)
        Sh[base + tid + i * 256] = __float2half_rn(v[i] * inv);
}

// ---------------- host ----------------
#define GETSYM(var, sym) cudaGetSymbolAddress((void**)&var, sym)

extern "C" void kernel_launch(void* const* d_in, const int* in_sizes, int n_in,
                              void* d_out, int out_size) {
    const float* x         = (const float*)d_in[0];
    const float* edge_attr = (const float*)d_in[1];
    const float* b         = (const float*)d_in[2];
    const int*   path_idx  = (const int*)d_in[3];
    const int*   path_len  = (const int*)d_in[4];
    const float* Wq        = (const float*)d_in[5];
    const float* bq        = (const float*)d_in[6];
    const float* Wk        = (const float*)d_in[7];
    const float* bk        = (const float*)d_in[8];
    const float* Wv        = (const float*)d_in[9];
    const float* bv        = (const float*)d_in[10];
    const float* edge_vec  = (const float*)d_in[11];
    const float* Wo        = (const float*)d_in[12];
    const float* bo        = (const float*)d_in[13];
    const float* ln1_g     = (const float*)d_in[14];
    const float* ln1_b     = (const float*)d_in[15];
    const float* ln2_g     = (const float*)d_in[16];
    const float* ln2_b     = (const float*)d_in[17];
    const float* W1        = (const float*)d_in[18];
    const float* b1        = (const float*)d_in[19];
    const float* W2        = (const float*)d_in[20];
    const float* b2        = (const float*)d_in[21];
    float* out = (float*)d_out;

    float *Sf, *x1f, *dmat, *bqkv;
    GETSYM(Sf, g_Sf); GETSYM(x1f, g_x1); GETSYM(dmat, g_dmat); GETSYM(bqkv, g_bqkv);
    h16 *xh, *QKVh, *Vth, *Sh, *mhh, *h2h, *ffh;
    h16 *Wh, *Woh, *W1h, *W2h;
    GETSYM(xh, g_xh);
    GETSYM(QKVh, g_QKVh);
    GETSYM(Vth, g_Vth);
    GETSYM(Sh, g_Sh);
    GETSYM(mhh, g_mhh);
    GETSYM(h2h, g_h2h);
    GETSYM(ffh, g_ffh);
    GETSYM(Wh, g_Wh);
    GETSYM(Woh, g_Woh);
    GETSYM(W1h, g_W1h);
    GETSYM(W2h, g_W2h);

    const int SM1 = 40960;
    cudaFuncSetAttribute(gemm_h<0>, cudaFuncAttributeMaxDynamicSharedMemorySize, SM1);
    cudaFuncSetAttribute(gemm_h<1>, cudaFuncAttributeMaxDynamicSharedMemorySize, SM1);
    cudaFuncSetAttribute(gemm_h<2>, cudaFuncAttributeMaxDynamicSharedMemorySize, SM1);
    cudaFuncSetAttribute(gemm_h<3>, cudaFuncAttributeMaxDynamicSharedMemorySize, SM1);

    const float scale = 1.0f / sqrtf((float)Dd);
    dim3 tb32(32, 8);
    const long ND = (long)Nn * Dd;
    const long NN = (long)Nn * Nn;
    const long DD = (long)Dd * Dd;

    // weight prep (transpose to K-major fp16, hi only)
    transpose_w<<<dim3(16, 16, Hh), tb32>>>(Wq, Wh, Dd, Dd, scale);
    transpose_w<<<dim3(16, 16, Hh), tb32>>>(Wk, Wh + 8 * DD, Dd, Dd, 1.f);
    transpose_w<<<dim3(16, 16, Hh), tb32>>>(Wv, Wh + 16 * DD, Dd, Dd, 1.f);
    transpose_w<<<dim3(16, 128, 1), tb32>>>(Wo, Woh, Hh * Dd, Dd, 1.f);
    transpose_w<<<dim3(64, 16, 1), tb32>>>(W1, W1h, Dd, Ff, 1.f);
    transpose_w<<<dim3(16, 64, 1), tb32>>>(W2, W2h, Ff, Dd, 1.f);
    pack_bias<<<48, 256>>>(bq, bk, bv, bqkv, scale);

    // LN1 (hi only), edge dots
    layernorm512_h<<<Nn, 128>>>(x, ln1_g, ln1_b, xh);
    edge_d_kernel<<<Ee / 4, 128>>>(edge_attr, edge_vec, dmat);

    // Q/K: batched 1-pass GEMM (16 batches), epilogue = +bias, fp16 out
    gemm_h<1><<<dim3(4, 16, 16), 256, SM1>>>(
        xh, Wh, nullptr, QKVh, bqkv, Dd, Dd, Dd, Dd, 0, DD, ND, Dd);

    // V^T directly: Vt[h][d][n] = sum_k Wv[h][k][d]*xln[n][k] + bv[h][d]
    gemm_h<3><<<dim3(16, 4, Hh), 256, SM1>>>(
        Wh + 16 * DD, xh, nullptr, Vth, bv, Dd, Dd, Dd, Nn, DD, 0, (long)Dd * Nn, Dd);

    // scores: S[h] = Qs @ K^T (fp32 out)
    gemm_h<0><<<dim3(16, 16, Hh), 256, SM1>>>(
        QKVh, QKVh + 8 * ND, Sf, nullptr, nullptr, Dd, Dd, Dd, Nn, ND, ND, NN, 0);

    // spatial + path bias, softmax -> fp16 hi only
    bias_c_softmax<<<dim3(Hh, Nn), 256>>>(Sf, b, path_idx, path_len, dmat, Sh);

    // attn @ V -> mh (fp16 out)
    gemm_h<1><<<dim3(4, 16, Hh), 256, SM1>>>(
        Sh, Vth, nullptr, mhh, nullptr, Nn, Nn, Nn, Hh * Dd, NN, (long)Dd * Nn, Dd, 0);

    // x1 = mh @ Wo + bo + x  (split-K=2 -> partials in Sf, fused reduce+LN2, hi only)
    gemm_h<0><<<dim3(4, 16, 2), 256, SM1>>>(
        mhh, Woh, Sf, nullptr, nullptr, Hh * Dd / 2, Hh * Dd, Hh * Dd, Dd,
        Hh * Dd / 2, Hh * Dd / 2, ND, 0);
    reduce2_ln_h<<<Nn, 128>>>(Sf, bo, x, ln2_g, ln2_b, x1f, h2h);

    // ff = gelu(h2 @ W1 + b1) (1-pass, fused gelu, hi only)
    gemm_h<2><<<dim3(16, 16, 1), 256, SM1>>>(
        h2h, W1h, nullptr, ffh, b1, Dd, Dd, Dd, Ff, 0, 0, 0, 0);

    // out = ff @ W2 + b2 + x1 (1-pass, split-K=2 -> reduce)
    gemm_h<0><<<dim3(4, 16, 2), 256, SM1>>>(
        ffh, W2h, Sf, nullptr, nullptr, Ff / 2, Ff, Ff, Dd, Ff / 2, Ff / 2, ND, 0);
    reduce2_bias_resid<<<(Nn * Dd) / 256, 256>>>(Sf, b2, x1f, out);
}